// round 13
// baseline (speedup 1.0000x reference)
#include <cuda_runtime.h>
#include <cuda_bf16.h>
#include <cuda_fp16.h>
#include <cstdint>

#define NB    8
#define NSEQ  1024
#define HIDD  768
#define NH    12
#define LR    256
#define HD    64

#define QT    128
#define KT    64
#define NIT   (NSEQ / KT)

// quantization scales (K_x*K_wl == K_xl*K_wh == 2^22)
#define QKX   16.0f
#define QKXL  8192.0f
#define QKWH  512.0f
#define QKWL  262144.0f
#define QINV  (1.0f / 4194304.0f)

// scratch (no cudaMalloc allowed)
__device__ uint32_t g_Xh [NB * NSEQ * (HIDD / 2)];   // X bf16 hi, k-pair packed
__device__ uint32_t g_Wh [NH * HD * (HIDD / 2)];     // Wc bf16 hi
__device__ uint32_t g_Xq [512 * 24 * 128];           // x int8 (full), A-frag layout
__device__ uint32_t g_Xl8[512 * 24 * 128];           // x residual int8, A-frag layout
__device__ uint32_t g_W8h[NH * 8 * 24 * 64];         // w int8, B-frag layout
__device__ uint32_t g_W8l[NH * 8 * 24 * 64];         // w residual int8, B-frag layout
__device__ uint32_t g_t16[NB * NH * NSEQ * (HD / 2)];// t fp16 e-pairs (q=k=v)

// ---------------------------------------------------------------------------
// helpers
// ---------------------------------------------------------------------------
__device__ __forceinline__ uint32_t smem_u32(const void* p) {
    uint32_t a;
    asm("{ .reg .u64 t; cvta.to.shared.u64 t, %1; cvt.u32.u64 %0, t; }"
        : "=r"(a) : "l"(p));
    return a;
}
__device__ __forceinline__ uint32_t packbf(float lo, float hi) {
    uint32_t r;
    asm("cvt.rn.bf16x2.f32 %0, %1, %2;" : "=r"(r) : "f"(hi), "f"(lo));
    return r;
}
__device__ __forceinline__ uint32_t packf16(float lo, float hi) {
    uint32_t r;
    asm("cvt.rn.f16x2.f32 %0, %1, %2;" : "=r"(r) : "f"(hi), "f"(lo));
    return r;
}
__device__ __forceinline__ int cvt8(float v) {
    int i = __float2int_rn(v);
    return max(-127, min(127, i));
}
__device__ __forceinline__ uint32_t pack8(int a, int b, int c, int d) {
    return (uint32_t)(a & 255) | ((uint32_t)(b & 255) << 8) |
           ((uint32_t)(c & 255) << 16) | ((uint32_t)(d & 255) << 24);
}
__device__ __forceinline__ float ex2(float x) {
    float r; asm("ex2.approx.f32 %0, %1;" : "=f"(r) : "f"(x)); return r;
}
// bf16 m16n8k16 (projection main term)
__device__ __forceinline__ void mma16(float* c, const uint32_t* a, const uint32_t* b) {
    asm volatile(
        "mma.sync.aligned.m16n8k16.row.col.f32.bf16.bf16.f32 "
        "{%0,%1,%2,%3}, {%4,%5,%6,%7}, {%8,%9}, {%0,%1,%2,%3};"
        : "+f"(c[0]), "+f"(c[1]), "+f"(c[2]), "+f"(c[3])
        : "r"(a[0]), "r"(a[1]), "r"(a[2]), "r"(a[3]), "r"(b[0]), "r"(b[1]));
}
// s8 m16n8k32 (projection correction terms)
__device__ __forceinline__ void mma32i(int* c, const uint4& a, const uint2& b) {
    asm volatile(
        "mma.sync.aligned.m16n8k32.row.col.s32.s8.s8.s32 "
        "{%0,%1,%2,%3}, {%4,%5,%6,%7}, {%8,%9}, {%0,%1,%2,%3};"
        : "+r"(c[0]), "+r"(c[1]), "+r"(c[2]), "+r"(c[3])
        : "r"(a.x), "r"(a.y), "r"(a.z), "r"(a.w), "r"(b.x), "r"(b.y));
}
// fp16 m16n8k16 (attention)
__device__ __forceinline__ void mma16h(float* c, const uint32_t* a, const uint32_t* b) {
    asm volatile(
        "mma.sync.aligned.m16n8k16.row.col.f32.f16.f16.f32 "
        "{%0,%1,%2,%3}, {%4,%5,%6,%7}, {%8,%9}, {%0,%1,%2,%3};"
        : "+f"(c[0]), "+f"(c[1]), "+f"(c[2]), "+f"(c[3])
        : "r"(a[0]), "r"(a[1]), "r"(a[2]), "r"(a[3]), "r"(b[0]), "r"(b[1]));
}
__device__ __forceinline__ void ldsm4(uint32_t* r, uint32_t a) {
    asm volatile("ldmatrix.sync.aligned.m8n8.x4.b16 {%0,%1,%2,%3}, [%4];"
        : "=r"(r[0]), "=r"(r[1]), "=r"(r[2]), "=r"(r[3]) : "r"(a));
}
__device__ __forceinline__ void ldsm4t(uint32_t* r, uint32_t a) {
    asm volatile("ldmatrix.sync.aligned.m8n8.x4.trans.b16 {%0,%1,%2,%3}, [%4];"
        : "=r"(r[0]), "=r"(r[1]), "=r"(r[2]), "=r"(r[3]) : "r"(a));
}

// ---------------------------------------------------------------------------
// Kernel 0: three branches by blockIdx.x
//  [0,144): Wc = Wa@Wt fp32, epilogue -> g_Wh (bf16) + g_W8h/g_W8l (int8 frags)
//  [144, 144+1536): X -> g_Xh (bf16 hi, row-major pairs)
//  [144+1536, +512): X -> g_Xq/g_Xl8 (int8, imma A-frag layout)
// ---------------------------------------------------------------------------
#define WC_BLKS  (NH * 12)
#define XH_BLKS  (NB * NSEQ * HIDD / 4096)   // 1536
#define XQ_BLKS  (NB * NSEQ / 16)            // 512

__global__ __launch_bounds__(256) void k_pre(const float* __restrict__ X,
                                             const float* __restrict__ Wt,
                                             const float* __restrict__ Wa) {
    const int bid = blockIdx.x;
    const int tid = threadIdx.x;

    if (bid >= WC_BLKS + XH_BLKS) {
        // ---- int8 A-frag split of X ----
        const int R = bid - WC_BLKS - XH_BLKS;      // 16-row block
        const int lid = tid & 31, wrp = tid >> 5;
        const int g = lid >> 2, t4 = lid & 3;
        const int r0 = R * 16 + g;
#pragma unroll
        for (int kb = 0; kb < 3; kb++) {
            const int Kb = wrp * 3 + kb;
            const int c0 = Kb * 32 + t4 * 4;
            float4 v[4];
            v[0] = *(const float4*)&X[(size_t)r0 * HIDD + c0];
            v[1] = *(const float4*)&X[(size_t)(r0 + 8) * HIDD + c0];
            v[2] = *(const float4*)&X[(size_t)r0 * HIDD + c0 + 16];
            v[3] = *(const float4*)&X[(size_t)(r0 + 8) * HIDD + c0 + 16];
            uint4 q, l8;
            uint32_t* qp = &q.x;
            uint32_t* lp = &l8.x;
#pragma unroll
            for (int i = 0; i < 4; i++) {
                float4 w = v[i];
                qp[i] = pack8(cvt8(w.x * QKX), cvt8(w.y * QKX),
                              cvt8(w.z * QKX), cvt8(w.w * QKX));
                uint32_t h01 = packbf(w.x, w.y);
                uint32_t h23 = packbf(w.z, w.w);
                float rx = w.x - __uint_as_float(h01 << 16);
                float ry = w.y - __uint_as_float(h01 & 0xffff0000u);
                float rz = w.z - __uint_as_float(h23 << 16);
                float rw = w.w - __uint_as_float(h23 & 0xffff0000u);
                lp[i] = pack8(cvt8(rx * QKXL), cvt8(ry * QKXL),
                              cvt8(rz * QKXL), cvt8(rw * QKXL));
            }
            size_t idx = ((size_t)R * 24 + Kb) * 32 + lid;
            *(uint4*)&g_Xq [idx * 4] = q;
            *(uint4*)&g_Xl8[idx * 4] = l8;
        }
        return;
    }
    if (bid >= WC_BLKS) {
        // ---- bf16-hi split of X (row-major pairs) ----
        size_t t = (size_t)(bid - WC_BLKS) * 256 + tid;
        float4 v[4];
#pragma unroll
        for (int i = 0; i < 4; i++) v[i] = *(const float4*)&X[t * 16 + i * 4];
        uint4 hp[2];
#pragma unroll
        for (int i = 0; i < 2; i++) {
            hp[i].x = packbf(v[i * 2].x, v[i * 2].y);
            hp[i].y = packbf(v[i * 2].z, v[i * 2].w);
            hp[i].z = packbf(v[i * 2 + 1].x, v[i * 2 + 1].y);
            hp[i].w = packbf(v[i * 2 + 1].z, v[i * 2 + 1].w);
        }
        *(uint4*)&g_Xh[t * 8]     = hp[0];
        *(uint4*)&g_Xh[t * 8 + 4] = hp[1];
        return;
    }

    // ---- Wc GEMM ----
    const int h  = bid / 12;
    const int d0 = (bid % 12) * 64;
    __shared__ float Wa_s[64 * 36];
    __shared__ float Wt_s[32 * 68];

    const int te = tid / 16;
    const int td = tid % 16;

    float acc[4][4];
#pragma unroll
    for (int i = 0; i < 4; i++)
#pragma unroll
        for (int j = 0; j < 4; j++) acc[i][j] = 0.f;

    for (int l0 = 0; l0 < LR; l0 += 32) {
#pragma unroll
        for (int it = 0; it < 2; it++) {
            int f = tid + it * 256;
            int e = f / 8, l4 = f % 8;
            float4 v = *(const float4*)&Wa[((size_t)h * 64 + e) * LR + l0 + l4 * 4];
            *(float4*)&Wa_s[e * 36 + l4 * 4] = v;
        }
#pragma unroll
        for (int it = 0; it < 2; it++) {
            int f = tid + it * 256;
            int l = f / 16, c4 = f % 16;
            float4 v = *(const float4*)&Wt[((size_t)h * LR + l0 + l) * HIDD + d0 + c4 * 4];
            *(float4*)&Wt_s[l * 68 + c4 * 4] = v;
        }
        __syncthreads();
#pragma unroll
        for (int l = 0; l < 32; l++) {
            float a[4];
#pragma unroll
            for (int i = 0; i < 4; i++) a[i] = Wa_s[(te * 4 + i) * 36 + l];
            float w[4];
            *(float4*)w = *(const float4*)&Wt_s[l * 68 + td * 4];
#pragma unroll
            for (int i = 0; i < 4; i++)
#pragma unroll
                for (int j = 0; j < 4; j++) acc[i][j] = fmaf(a[i], w[j], acc[i][j]);
        }
        __syncthreads();
    }
    // epilogue: bf16-hi pairs + int8 B-frag words
    const int Kb = (d0 + td * 4) >> 5;
    const int t4p = td & 3;
    const int half = (td >> 2) & 1;
#pragma unroll
    for (int i = 0; i < 4; i++) {
        const int e = te * 4 + i;
        uint32_t hp0 = packbf(acc[i][0], acc[i][1]);
        uint32_t hp1 = packbf(acc[i][2], acc[i][3]);
        size_t base = ((size_t)h * HD + e) * (HIDD / 2) + d0 / 2 + td * 2;
        *(uint2*)&g_Wh[base] = make_uint2(hp0, hp1);
        float r0 = acc[i][0] - __uint_as_float(hp0 << 16);
        float r1 = acc[i][1] - __uint_as_float(hp0 & 0xffff0000u);
        float r2 = acc[i][2] - __uint_as_float(hp1 << 16);
        float r3 = acc[i][3] - __uint_as_float(hp1 & 0xffff0000u);
        uint32_t wq = pack8(cvt8(acc[i][0] * QKWH), cvt8(acc[i][1] * QKWH),
                            cvt8(acc[i][2] * QKWH), cvt8(acc[i][3] * QKWH));
        uint32_t wl = pack8(cvt8(r0 * QKWL), cvt8(r1 * QKWL),
                            cvt8(r2 * QKWL), cvt8(r3 * QKWL));
        const int E = e >> 3, gp = e & 7;
        size_t widx = ((size_t)h * 8 + E) * 24 * 64
                    + (size_t)Kb * 64 + (gp * 4 + t4p) * 2 + half;
        g_W8h[widx] = wq;
        g_W8l[widx] = wl;
    }
}

// ---------------------------------------------------------------------------
// Kernel 1: t = X*Wc^T. Main term bf16 k16 + int8 k32 correction terms.
// CTA: 128 n x 64 e of one (b,h); 8 warps (4m x 2n); K-tile 32, 2 stages.
// ---------------------------------------------------------------------------
#define PJ_XH   0                      // 128*80
#define PJ_WH   10240                  // 64*80
#define PJ_XQ   15360                  // 4096 (A-frag)
#define PJ_XL8  19456                  // 4096
#define PJ_W8H  23552                  // 2048 (B-frag)
#define PJ_W8L  25600                  // 2048
#define PJ_STG  27648
#define PROJ_SMEM_BYTES (2 * PJ_STG)
#define NKIT  (HIDD / 32)              // 24

__global__ __launch_bounds__(256, 2) void k_proj_mma(int dummy) {
    extern __shared__ __align__(128) char smem[];
    const uint32_t smb = smem_u32(smem);

    const int bh = blockIdx.y, b = bh / NH, h = bh % NH;
    const int n0 = blockIdx.x * 128;
    const int tid = threadIdx.x, wid = tid >> 5, lid = tid & 31;
    const int mw = wid & 3, nw = wid >> 2;
    const int g = lid >> 2, t4 = lid & 3;
    const int mrow = mw * 32, ncol = nw * 32;
    const int l7 = lid & 7;
    const int r8  = (lid & 8)  ? 8 : 0;
    const int r16 = (lid & 16) ? 8 : 0;

    const uint32_t* Xhg = g_Xh + (size_t)(b * NSEQ + n0) * (HIDD / 2);
    const uint32_t* Whg = g_Wh + (size_t)h * HD * (HIDD / 2);
    const int R0 = (b * NSEQ + n0) / 16;

    auto issue = [&](int ki) {
        const uint32_t sb = smb + (ki & 1) * PJ_STG;
        const int k4 = ki * 16;
        // Xh bf16: 128 rows x 64B
#pragma unroll
        for (int it = 0; it < 2; it++) {
            int f = tid + it * 256;
            int r = f >> 2, c = f & 3;
            asm volatile("cp.async.cg.shared.global [%0], [%1], 16;"
                         :: "r"(sb + PJ_XH + (uint32_t)(r * 80 + c * 16)),
                            "l"(Xhg + (size_t)r * 384 + k4 + c * 4));
        }
        // Wh bf16: 64 rows x 64B
        {
            int r = tid >> 2, c = tid & 3;
            asm volatile("cp.async.cg.shared.global [%0], [%1], 16;"
                         :: "r"(sb + PJ_WH + (uint32_t)(r * 80 + c * 16)),
                            "l"(Whg + (size_t)r * 384 + k4 + c * 4));
        }
        // Xq / Xl8 A-frags: 8 rb x 512B each
        {
            int rb = tid >> 5, l = tid & 31;
            size_t src = (((size_t)(R0 + rb) * 24 + ki) * 32 + l) * 4;
            asm volatile("cp.async.cg.shared.global [%0], [%1], 16;"
                         :: "r"(sb + PJ_XQ + (uint32_t)(rb * 512 + l * 16)),
                            "l"(g_Xq + src));
            asm volatile("cp.async.cg.shared.global [%0], [%1], 16;"
                         :: "r"(sb + PJ_XL8 + (uint32_t)(rb * 512 + l * 16)),
                            "l"(g_Xl8 + src));
        }
        // W8h / W8l B-frags: 8 E x 256B each (split across thread halves)
        {
            int tt = tid & 127;
            int E = tt >> 4, ch = tt & 15;
            size_t src = ((size_t)h * 8 + E) * 24 * 64 + (size_t)ki * 64 + ch * 4;
            uint32_t dst = sb + (uint32_t)(E * 256 + ch * 16);
            if (tid < 128) {
                asm volatile("cp.async.cg.shared.global [%0], [%1], 16;"
                             :: "r"(dst + PJ_W8H), "l"(g_W8h + src));
            } else {
                asm volatile("cp.async.cg.shared.global [%0], [%1], 16;"
                             :: "r"(dst + PJ_W8L), "l"(g_W8l + src));
            }
        }
        asm volatile("cp.async.commit_group;" ::: "memory");
    };

    float accf[2][4][4];
    int   acci[2][4][4];
#pragma unroll
    for (int mi = 0; mi < 2; mi++)
#pragma unroll
        for (int nj = 0; nj < 4; nj++)
#pragma unroll
            for (int r = 0; r < 4; r++) { accf[mi][nj][r] = 0.f; acci[mi][nj][r] = 0; }

    const uint32_t aro = (uint32_t)((mrow + l7 + r8) * 80 + r16 * 2);
    const uint32_t bro = (uint32_t)((ncol + l7 + r16) * 80 + r8 * 2);

    issue(0);
#pragma unroll 1
    for (int ki = 0; ki < NKIT; ki++) {
        asm volatile("cp.async.wait_group 0;" ::: "memory");
        __syncthreads();
        if (ki + 1 < NKIT) issue(ki + 1);

        const uint32_t sb = smb + (ki & 1) * PJ_STG;
        const char* sc = smem + (ki & 1) * PJ_STG;

        // ---- main term: Xh*Wh bf16 ----
#pragma unroll
        for (int c16 = 0; c16 < 2; c16++) {
            const uint32_t off = c16 * 32;
            uint32_t xh0[4], xh1[4], wh0[4], wh1[4];
            ldsm4(xh0, sb + PJ_XH + aro + off);
            ldsm4(xh1, sb + PJ_XH + aro + 16 * 80 + off);
            ldsm4(wh0, sb + PJ_WH + bro + off);
            ldsm4(wh1, sb + PJ_WH + bro + 16 * 80 + off);
            mma16(accf[0][0], xh0, wh0);
            mma16(accf[0][1], xh0, wh0 + 2);
            mma16(accf[0][2], xh0, wh1);
            mma16(accf[0][3], xh0, wh1 + 2);
            mma16(accf[1][0], xh1, wh0);
            mma16(accf[1][1], xh1, wh0 + 2);
            mma16(accf[1][2], xh1, wh1);
            mma16(accf[1][3], xh1, wh1 + 2);
        }

        // ---- correction terms: xq*wl8 + xl8*wh8 (s8 k32) ----
        uint4 xq[2], xl[2];
#pragma unroll
        for (int mi = 0; mi < 2; mi++) {
            xq[mi] = *(const uint4*)(sc + PJ_XQ  + (2 * mw + mi) * 512 + lid * 16);
            xl[mi] = *(const uint4*)(sc + PJ_XL8 + (2 * mw + mi) * 512 + lid * 16);
        }
#pragma unroll
        for (int nj = 0; nj < 4; nj++) {
            uint2 wh8 = *(const uint2*)(sc + PJ_W8H + (4 * nw + nj) * 256 + lid * 8);
            uint2 wl8 = *(const uint2*)(sc + PJ_W8L + (4 * nw + nj) * 256 + lid * 8);
#pragma unroll
            for (int mi = 0; mi < 2; mi++) {
                mma32i(acci[mi][nj], xq[mi], wl8);
                mma32i(acci[mi][nj], xl[mi], wh8);
            }
        }
    }

    // epilogue: combine + fp16 t
    uint32_t* T16 = g_t16 + ((size_t)bh * NSEQ + n0) * (HD / 2);
#pragma unroll
    for (int mi = 0; mi < 2; mi++) {
        int r0 = mrow + mi * 16 + g;
#pragma unroll
        for (int nj = 0; nj < 4; nj++) {
            float t0 = accf[mi][nj][0] + (float)acci[mi][nj][0] * QINV;
            float t1 = accf[mi][nj][1] + (float)acci[mi][nj][1] * QINV;
            float t2 = accf[mi][nj][2] + (float)acci[mi][nj][2] * QINV;
            float t3 = accf[mi][nj][3] + (float)acci[mi][nj][3] * QINV;
            int cu = (ncol + nj * 8) / 2 + t4;
            T16[(size_t)r0 * (HD / 2) + cu]       = packf16(t0, t1);
            T16[(size_t)(r0 + 8) * (HD / 2) + cu] = packf16(t2, t3);
        }
    }
}

// ---------------------------------------------------------------------------
// Kernel 2: all-fp16 flash attention (unchanged from round 12).
// ---------------------------------------------------------------------------
#define A_Q    0
#define A_KV   18432
#define A_KVST 9216
#define A_OB   36864
#define A_OL   37376
#define A_SM   37888

#define CE 0.052058774f

__global__ __launch_bounds__(256, 2) void k_attn7(const int* __restrict__ amask,
                                                  float* __restrict__ out) {
    extern __shared__ __align__(128) char smem[];
    const uint32_t smb = smem_u32(smem);

    const int bh = blockIdx.y, b = bh / NH, h = bh % NH;
    const int q0 = blockIdx.x * QT;
    const int tid = threadIdx.x, wid = tid >> 5, lid = tid & 31;
    const int g = lid >> 2, t4 = lid & 3;
    const int w16 = wid * 16;
    const int l7 = lid & 7;
    const int r8  = (lid & 8)  ? 8 : 0;
    const int r16 = (lid & 16) ? 8 : 0;

    const uint32_t* T16 = g_t16 + (size_t)bh * NSEQ * (HD / 2);
    const int* mb = amask + (size_t)b * NSEQ;
    float* biasf = (float*)(smem + A_OB);

#pragma unroll
    for (int it = 0; it < 4; it++) {
        int f = tid + it * 256;
        int r = f >> 3, c = f & 7;
        uint32_t dst = smb + A_Q + (uint32_t)(r * 144 + c * 16);
        asm volatile("cp.async.cg.shared.global [%0], [%1], 16;"
                     :: "r"(dst), "l"(T16 + (size_t)(q0 + r) * 32 + c * 4));
    }
#pragma unroll
    for (int it = 0; it < 2; it++) {
        int f = tid + it * 256;
        int r = f >> 3, c = f & 7;
        uint32_t dst = smb + A_KV + (uint32_t)(r * 144 + c * 16);
        asm volatile("cp.async.cg.shared.global [%0], [%1], 16;"
                     :: "r"(dst), "l"(T16 + (size_t)r * 32 + c * 4));
    }
    asm volatile("cp.async.commit_group;" ::: "memory");
    if (tid < 64) biasf[tid] = (mb[tid] == 0) ? -3000.f : 0.f;

    float rs0 = 0.f, rs1 = 0.f;
    float oacc[4][2][4];
#pragma unroll
    for (int me = 0; me < 4; me++)
#pragma unroll
        for (int n = 0; n < 2; n++)
#pragma unroll
            for (int r = 0; r < 4; r++) oacc[me][n][r] = 0.f;

    const uint32_t qro = (uint32_t)((w16 + l7 + r8) * 144 + r16 * 2);
    const uint32_t kro = (uint32_t)((l7 + r16) * 144 + r8 * 2);

#pragma unroll 1
    for (int i = 0; i < NIT; i++) {
        asm volatile("cp.async.wait_group 0;" ::: "memory");
        __syncthreads();

        if (i + 1 < NIT) {
            int j0 = (i + 1) * KT;
            uint32_t kst = A_KV + ((i + 1) & 1) * A_KVST;
#pragma unroll
            for (int it = 0; it < 2; it++) {
                int f = tid + it * 256;
                int r = f >> 3, c = f & 7;
                uint32_t dst = smb + kst + (uint32_t)(r * 144 + c * 16);
                asm volatile("cp.async.cg.shared.global [%0], [%1], 16;"
                             :: "r"(dst), "l"(T16 + (size_t)(j0 + r) * 32 + c * 4));
            }
            asm volatile("cp.async.commit_group;" ::: "memory");
            if (tid < 64)
                biasf[((i + 1) & 1) * 64 + tid] =
                    (mb[j0 + tid] == 0) ? -3000.f : 0.f;
        }

        const uint32_t kvb = smb + A_KV + (i & 1) * A_KVST;

        float sacc[8][4];
#pragma unroll
        for (int kg = 0; kg < 8; kg++)
#pragma unroll
            for (int r = 0; r < 4; r++) sacc[kg][r] = 0.f;

#pragma unroll
        for (int kb = 0; kb < 4; kb++) {
            uint32_t qf[4];
            ldsm4(qf, smb + A_Q + qro + kb * 32);
#pragma unroll
            for (int kt = 0; kt < 4; kt++) {
                uint32_t kf[4];
                ldsm4(kf, kvb + (uint32_t)(kt * 16 * 144) + kro + kb * 32);
                mma16h(sacc[kt * 2],     qf, kf);
                mma16h(sacc[kt * 2 + 1], qf, kf + 2);
            }
        }

        uint32_t u01[8], u23[8];
        const float* bi = biasf + (i & 1) * 64;
#pragma unroll
        for (int kg = 0; kg < 8; kg++) {
            float bx = bi[kg * 8 + 2 * t4];
            float by = bi[kg * 8 + 2 * t4 + 1];
            float* c = sacc[kg];
            float p0 = ex2(fmaf(c[0], CE, bx));
            float p1 = ex2(fmaf(c[1], CE, by));
            float p2 = ex2(fmaf(c[2], CE, bx));
            float p3 = ex2(fmaf(c[3], CE, by));
            rs0 += p0 + p1;
            rs1 += p2 + p3;
            u01[kg] = packf16(p0, p1);
            u23[kg] = packf16(p2, p3);
        }

#pragma unroll
        for (int kt = 0; kt < 4; kt++) {
            uint32_t b0[2] = { u01[kt * 2], u01[kt * 2 + 1] };
            uint32_t b1[2] = { u23[kt * 2], u23[kt * 2 + 1] };
#pragma unroll
            for (int me = 0; me < 4; me++) {
                uint32_t ah[4];
                ldsm4t(ah, kvb + (uint32_t)((kt * 16 + l7 + r16) * 144
                                            + (me * 16 + r8) * 2));
                mma16h(oacc[me][0], ah, b0);
                mma16h(oacc[me][1], ah, b1);
            }
        }
    }

    rs0 += __shfl_xor_sync(0xffffffffu, rs0, 1);
    rs0 += __shfl_xor_sync(0xffffffffu, rs0, 2);
    rs1 += __shfl_xor_sync(0xffffffffu, rs1, 1);
    rs1 += __shfl_xor_sync(0xffffffffu, rs1, 2);
    float* lred = (float*)(smem + A_OL);
    if (t4 == 0) {
        lred[w16 + g] = rs0;
        lred[w16 + 8 + g] = rs1;
    }
    __syncthreads();

    const int qa = w16 + 2 * t4;
    const float inv0 = 1.f / lred[qa];
    const float inv1 = 1.f / lred[qa + 1];
    const float inv2 = 1.f / lred[qa + 8];
    const float inv3 = 1.f / lred[qa + 9];
    float* ob = out + ((size_t)b * NSEQ + q0 + qa) * (NH * HD) + h * HD;
#pragma unroll
    for (int me = 0; me < 4; me++) {
        int e0 = me * 16 + g;
        ob[e0]                   = oacc[me][0][0] * inv0;
        ob[NH * HD + e0]         = oacc[me][0][1] * inv1;
        ob[e0 + 8]               = oacc[me][0][2] * inv0;
        ob[NH * HD + e0 + 8]     = oacc[me][0][3] * inv1;
        ob[8 * NH * HD + e0]     = oacc[me][1][0] * inv2;
        ob[9 * NH * HD + e0]     = oacc[me][1][1] * inv3;
        ob[8 * NH * HD + e0 + 8] = oacc[me][1][2] * inv2;
        ob[9 * NH * HD + e0 + 8] = oacc[me][1][3] * inv3;
    }
}

// ---------------------------------------------------------------------------
extern "C" void kernel_launch(void* const* d_in, const int* in_sizes, int n_in,
                              void* d_out, int out_size) {
    const float* hidden = (const float*)d_in[0];
    const int*   amask  = (const int*)d_in[1];
    const float* Wt     = (const float*)d_in[2];
    const float* Wa     = (const float*)d_in[3];
    float* out = (float*)d_out;

    k_pre<<<WC_BLKS + XH_BLKS + XQ_BLKS, 256>>>(hidden, Wt, Wa);

    cudaFuncSetAttribute(k_proj_mma, cudaFuncAttributeMaxDynamicSharedMemorySize,
                         PROJ_SMEM_BYTES);
    k_proj_mma<<<dim3(NSEQ / 128, NB * NH), 256, PROJ_SMEM_BYTES>>>(0);

    cudaFuncSetAttribute(k_attn7, cudaFuncAttributeMaxDynamicSharedMemorySize,
                         A_SM);
    k_attn7<<<dim3(NSEQ / QT, NB * NH), 256, A_SM>>>(amask, out);
}

// round 14
// speedup vs baseline: 1.4094x; 1.4094x over previous
#include <cuda_runtime.h>
#include <cuda_bf16.h>
#include <cuda_fp16.h>
#include <cstdint>

#define NB    8
#define NSEQ  1024
#define HIDD  768
#define NH    12
#define LR    256
#define HD    64

#define QT    128
#define KT    64
#define NIT   (NSEQ / KT)

// scratch (no cudaMalloc allowed)
__device__ uint32_t g_Xh[NB * NSEQ * (HIDD / 2)];    // X bf16 hi, k-pair packed
__device__ uint32_t g_Xl[NB * NSEQ * (HIDD / 2)];
__device__ uint32_t g_Wh[NH * HD * (HIDD / 2)];      // Wc bf16 hi
__device__ uint32_t g_Wl[NH * HD * (HIDD / 2)];
__device__ uint32_t g_t16[NB * NH * NSEQ * (HD / 2)];// t fp16 e-pairs (q=k=v)

// ---------------------------------------------------------------------------
// helpers
// ---------------------------------------------------------------------------
__device__ __forceinline__ uint32_t smem_u32(const void* p) {
    uint32_t a;
    asm("{ .reg .u64 t; cvta.to.shared.u64 t, %1; cvt.u32.u64 %0, t; }"
        : "=r"(a) : "l"(p));
    return a;
}
__device__ __forceinline__ uint32_t packbf(float lo, float hi) {
    uint32_t r;
    asm("cvt.rn.bf16x2.f32 %0, %1, %2;" : "=r"(r) : "f"(hi), "f"(lo));
    return r;
}
__device__ __forceinline__ uint32_t packf16(float lo, float hi) {
    uint32_t r;
    asm("cvt.rn.f16x2.f32 %0, %1, %2;" : "=r"(r) : "f"(hi), "f"(lo));
    return r;
}
__device__ __forceinline__ void split2(float x0, float x1,
                                       uint32_t& hp, uint32_t& lp) {
    hp = packbf(x0, x1);
    float h0 = __uint_as_float(hp << 16);
    float h1 = __uint_as_float(hp & 0xffff0000u);
    lp = packbf(x0 - h0, x1 - h1);
}
__device__ __forceinline__ float ex2(float x) {
    float r; asm("ex2.approx.f32 %0, %1;" : "=f"(r) : "f"(x)); return r;
}
// bf16 m16n8k16 (projection)
__device__ __forceinline__ void mma16(float* c, const uint32_t* a, const uint32_t* b) {
    asm volatile(
        "mma.sync.aligned.m16n8k16.row.col.f32.bf16.bf16.f32 "
        "{%0,%1,%2,%3}, {%4,%5,%6,%7}, {%8,%9}, {%0,%1,%2,%3};"
        : "+f"(c[0]), "+f"(c[1]), "+f"(c[2]), "+f"(c[3])
        : "r"(a[0]), "r"(a[1]), "r"(a[2]), "r"(a[3]), "r"(b[0]), "r"(b[1]));
}
// fp16 m16n8k16 (attention S and PV)
__device__ __forceinline__ void mma16h(float* c, const uint32_t* a, const uint32_t* b) {
    asm volatile(
        "mma.sync.aligned.m16n8k16.row.col.f32.f16.f16.f32 "
        "{%0,%1,%2,%3}, {%4,%5,%6,%7}, {%8,%9}, {%0,%1,%2,%3};"
        : "+f"(c[0]), "+f"(c[1]), "+f"(c[2]), "+f"(c[3])
        : "r"(a[0]), "r"(a[1]), "r"(a[2]), "r"(a[3]), "r"(b[0]), "r"(b[1]));
}
__device__ __forceinline__ void ldsm4(uint32_t* r, uint32_t a) {
    asm volatile("ldmatrix.sync.aligned.m8n8.x4.b16 {%0,%1,%2,%3}, [%4];"
        : "=r"(r[0]), "=r"(r[1]), "=r"(r[2]), "=r"(r[3]) : "r"(a));
}
__device__ __forceinline__ void ldsm4t(uint32_t* r, uint32_t a) {
    asm volatile("ldmatrix.sync.aligned.m8n8.x4.trans.b16 {%0,%1,%2,%3}, [%4];"
        : "=r"(r[0]), "=r"(r[1]), "=r"(r[2]), "=r"(r[3]) : "r"(a));
}

// ---------------------------------------------------------------------------
// Kernel 0 (merged): blocks [0,144): Wc = Wa@Wt (fp32) -> bf16 h/l
//   blocks [144, 144+768): split X -> bf16 h/l (32 floats/thread, 8x LDG.128)
// ---------------------------------------------------------------------------
#define WC_BLKS  (NH * 12)
#define CVT_BLKS (NB * NSEQ * HIDD / 8192)   // 768

__global__ __launch_bounds__(256) void k_pre(const float* __restrict__ X,
                                             const float* __restrict__ Wt,
                                             const float* __restrict__ Wa) {
    if (blockIdx.x >= WC_BLKS) {
        size_t t = (size_t)(blockIdx.x - WC_BLKS) * 256 + threadIdx.x;
        float4 v[8];
#pragma unroll
        for (int i = 0; i < 8; i++) v[i] = *(const float4*)&X[t * 32 + i * 4];
        uint4 hp[4], lp[4];
#pragma unroll
        for (int i = 0; i < 4; i++) {
            split2(v[i * 2].x, v[i * 2].y, hp[i].x, lp[i].x);
            split2(v[i * 2].z, v[i * 2].w, hp[i].y, lp[i].y);
            split2(v[i * 2 + 1].x, v[i * 2 + 1].y, hp[i].z, lp[i].z);
            split2(v[i * 2 + 1].z, v[i * 2 + 1].w, hp[i].w, lp[i].w);
        }
#pragma unroll
        for (int i = 0; i < 4; i++) {
            *(uint4*)&g_Xh[t * 16 + i * 4] = hp[i];
            *(uint4*)&g_Xl[t * 16 + i * 4] = lp[i];
        }
        return;
    }
    const int h  = blockIdx.x / 12;
    const int d0 = (blockIdx.x % 12) * 64;
    __shared__ float Wa_s[64 * 36];
    __shared__ float Wt_s[32 * 68];

    const int tid = threadIdx.x;
    const int te = tid / 16;
    const int td = tid % 16;

    float acc[4][4];
#pragma unroll
    for (int i = 0; i < 4; i++)
#pragma unroll
        for (int j = 0; j < 4; j++) acc[i][j] = 0.f;

    for (int l0 = 0; l0 < LR; l0 += 32) {
#pragma unroll
        for (int it = 0; it < 2; it++) {
            int f = tid + it * 256;
            int e = f / 8, l4 = f % 8;
            float4 v = *(const float4*)&Wa[((size_t)h * 64 + e) * LR + l0 + l4 * 4];
            *(float4*)&Wa_s[e * 36 + l4 * 4] = v;
        }
#pragma unroll
        for (int it = 0; it < 2; it++) {
            int f = tid + it * 256;
            int l = f / 16, c4 = f % 16;
            float4 v = *(const float4*)&Wt[((size_t)h * LR + l0 + l) * HIDD + d0 + c4 * 4];
            *(float4*)&Wt_s[l * 68 + c4 * 4] = v;
        }
        __syncthreads();
#pragma unroll
        for (int l = 0; l < 32; l++) {
            float a[4];
#pragma unroll
            for (int i = 0; i < 4; i++) a[i] = Wa_s[(te * 4 + i) * 36 + l];
            float w[4];
            *(float4*)w = *(const float4*)&Wt_s[l * 68 + td * 4];
#pragma unroll
            for (int i = 0; i < 4; i++)
#pragma unroll
                for (int j = 0; j < 4; j++) acc[i][j] = fmaf(a[i], w[j], acc[i][j]);
        }
        __syncthreads();
    }
#pragma unroll
    for (int i = 0; i < 4; i++) {
        uint32_t h0, l0u, h1, l1u;
        split2(acc[i][0], acc[i][1], h0, l0u);
        split2(acc[i][2], acc[i][3], h1, l1u);
        size_t base = ((size_t)h * HD + te * 4 + i) * (HIDD / 2) + d0 / 2 + td * 2;
        *(uint2*)&g_Wh[base] = make_uint2(h0, h1);
        *(uint2*)&g_Wl[base] = make_uint2(l0u, l1u);
    }
}

// ---------------------------------------------------------------------------
// Kernel 1: t = X * Wc^T, 3-term bf16 split, ldmatrix frags, single-sync loop.
// ---------------------------------------------------------------------------
#define PJ_X    0                      // per stage: Xh 128*80, Xl at +10240
#define PJ_XST  20480
#define PJ_W    40960                  // per stage: Wh 64*80, Wl at +5120
#define PJ_WST  10240
#define PROJ_SMEM_BYTES 61440
#define NKIT  (HIDD / 32)              // 24

__global__ __launch_bounds__(256, 2) void k_proj_mma(int dummy) {
    extern __shared__ __align__(128) char smem[];
    const uint32_t smb = smem_u32(smem);

    const int bh = blockIdx.y, b = bh / NH, h = bh % NH;
    const int n0 = blockIdx.x * 128;
    const int tid = threadIdx.x, wid = tid >> 5, lid = tid & 31;
    const int mw = wid & 3, nw = wid >> 2;
    const int g = lid >> 2, t4 = lid & 3;
    const int mrow = mw * 32, ncol = nw * 32;
    const int l7 = lid & 7;
    const int r8  = (lid & 8)  ? 8 : 0;
    const int r16 = (lid & 16) ? 8 : 0;

    const uint32_t* Xh = g_Xh + (size_t)(b * NSEQ + n0) * (HIDD / 2);
    const uint32_t* Xl = g_Xl + (size_t)(b * NSEQ + n0) * (HIDD / 2);
    const uint32_t* Wh = g_Wh + (size_t)h * HD * (HIDD / 2);
    const uint32_t* Wl = g_Wl + (size_t)h * HD * (HIDD / 2);

    auto issue = [&](int ki) {
        const uint32_t xb = smb + PJ_X + (ki & 1) * PJ_XST;
        const uint32_t wb = smb + PJ_W + (ki & 1) * PJ_WST;
        const int k4 = ki * 16;
#pragma unroll
        for (int it = 0; it < 2; it++) {
            int f = tid + it * 256;
            int r = f >> 2, c = f & 3;
            uint32_t d = (uint32_t)(r * 80 + c * 16);
            asm volatile("cp.async.cg.shared.global [%0], [%1], 16;"
                         :: "r"(xb + d), "l"(Xh + (size_t)r * 384 + k4 + c * 4));
            asm volatile("cp.async.cg.shared.global [%0], [%1], 16;"
                         :: "r"(xb + 10240 + d), "l"(Xl + (size_t)r * 384 + k4 + c * 4));
        }
        {
            int r = tid >> 2, c = tid & 3;
            uint32_t d = (uint32_t)(r * 80 + c * 16);
            asm volatile("cp.async.cg.shared.global [%0], [%1], 16;"
                         :: "r"(wb + d), "l"(Wh + (size_t)r * 384 + k4 + c * 4));
            asm volatile("cp.async.cg.shared.global [%0], [%1], 16;"
                         :: "r"(wb + 5120 + d), "l"(Wl + (size_t)r * 384 + k4 + c * 4));
        }
        asm volatile("cp.async.commit_group;" ::: "memory");
    };

    float acc[2][4][4];
#pragma unroll
    for (int mi = 0; mi < 2; mi++)
#pragma unroll
        for (int nj = 0; nj < 4; nj++)
#pragma unroll
            for (int r = 0; r < 4; r++) acc[mi][nj][r] = 0.f;

    const uint32_t aro = (uint32_t)((mrow + l7 + r8) * 80 + r16 * 2);
    const uint32_t bro = (uint32_t)((ncol + l7 + r16) * 80 + r8 * 2);

    issue(0);
#pragma unroll 1
    for (int ki = 0; ki < NKIT; ki++) {
        asm volatile("cp.async.wait_group 0;" ::: "memory");
        __syncthreads();
        if (ki + 1 < NKIT) issue(ki + 1);

        const uint32_t xb = smb + PJ_X + (ki & 1) * PJ_XST;
        const uint32_t wb = smb + PJ_W + (ki & 1) * PJ_WST;
#pragma unroll
        for (int c16 = 0; c16 < 2; c16++) {
            const uint32_t off = c16 * 32;
            uint32_t xh0[4], xh1[4], xl0[4], xl1[4];
            ldsm4(xh0, xb + aro + off);
            ldsm4(xh1, xb + aro + 16 * 80 + off);
            ldsm4(xl0, xb + 10240 + aro + off);
            ldsm4(xl1, xb + 10240 + aro + 16 * 80 + off);
            uint32_t wh0[4], wh1[4], wl0[4], wl1[4];
            ldsm4(wh0, wb + bro + off);
            ldsm4(wh1, wb + bro + 16 * 80 + off);
            ldsm4(wl0, wb + 5120 + bro + off);
            ldsm4(wl1, wb + 5120 + bro + 16 * 80 + off);
            mma16(acc[0][0], xh0, wh0);     mma16(acc[0][0], xh0, wl0);
            mma16(acc[0][0], xl0, wh0);
            mma16(acc[0][1], xh0, wh0 + 2); mma16(acc[0][1], xh0, wl0 + 2);
            mma16(acc[0][1], xl0, wh0 + 2);
            mma16(acc[0][2], xh0, wh1);     mma16(acc[0][2], xh0, wl1);
            mma16(acc[0][2], xl0, wh1);
            mma16(acc[0][3], xh0, wh1 + 2); mma16(acc[0][3], xh0, wl1 + 2);
            mma16(acc[0][3], xl0, wh1 + 2);
            mma16(acc[1][0], xh1, wh0);     mma16(acc[1][0], xh1, wl0);
            mma16(acc[1][0], xl1, wh0);
            mma16(acc[1][1], xh1, wh0 + 2); mma16(acc[1][1], xh1, wl0 + 2);
            mma16(acc[1][1], xl1, wh0 + 2);
            mma16(acc[1][2], xh1, wh1);     mma16(acc[1][2], xh1, wl1);
            mma16(acc[1][2], xl1, wh1);
            mma16(acc[1][3], xh1, wh1 + 2); mma16(acc[1][3], xh1, wl1 + 2);
            mma16(acc[1][3], xl1, wh1 + 2);
        }
    }

    // epilogue: fp16 t
    uint32_t* T16 = g_t16 + ((size_t)bh * NSEQ + n0) * (HD / 2);
#pragma unroll
    for (int mi = 0; mi < 2; mi++) {
        int r0 = mrow + mi * 16 + g;
#pragma unroll
        for (int nj = 0; nj < 4; nj++) {
            int cu = (ncol + nj * 8) / 2 + t4;
            T16[(size_t)r0 * (HD / 2) + cu] =
                packf16(acc[mi][nj][0], acc[mi][nj][1]);
            T16[(size_t)(r0 + 8) * (HD / 2) + cu] =
                packf16(acc[mi][nj][2], acc[mi][nj][3]);
        }
    }
}

// ---------------------------------------------------------------------------
// Kernel 2: all-fp16 flash attention; exp via MUFU ex2.approx.
// ---------------------------------------------------------------------------
#define A_Q    0                    // 128 * 144 fp16
#define A_KV   18432                // 2 stages * 64*144
#define A_KVST 9216
#define A_OB   36864                // float[2][64]
#define A_OL   37376                // float[128]
#define A_SM   37888

#define CE 0.052058774f             // 768^-0.5 * log2(e)

__global__ __launch_bounds__(256, 2) void k_attn7(const int* __restrict__ amask,
                                                  float* __restrict__ out) {
    extern __shared__ __align__(128) char smem[];
    const uint32_t smb = smem_u32(smem);

    const int bh = blockIdx.y, b = bh / NH, h = bh % NH;
    const int q0 = blockIdx.x * QT;
    const int tid = threadIdx.x, wid = tid >> 5, lid = tid & 31;
    const int g = lid >> 2, t4 = lid & 3;
    const int w16 = wid * 16;
    const int l7 = lid & 7;
    const int r8  = (lid & 8)  ? 8 : 0;
    const int r16 = (lid & 16) ? 8 : 0;

    const uint32_t* T16 = g_t16 + (size_t)bh * NSEQ * (HD / 2);
    const int* mb = amask + (size_t)b * NSEQ;
    float* biasf = (float*)(smem + A_OB);

    // prologue: Q fp16, KV tile 0, bias 0
#pragma unroll
    for (int it = 0; it < 4; it++) {
        int f = tid + it * 256;
        int r = f >> 3, c = f & 7;
        uint32_t dst = smb + A_Q + (uint32_t)(r * 144 + c * 16);
        asm volatile("cp.async.cg.shared.global [%0], [%1], 16;"
                     :: "r"(dst), "l"(T16 + (size_t)(q0 + r) * 32 + c * 4));
    }
#pragma unroll
    for (int it = 0; it < 2; it++) {
        int f = tid + it * 256;
        int r = f >> 3, c = f & 7;
        uint32_t dst = smb + A_KV + (uint32_t)(r * 144 + c * 16);
        asm volatile("cp.async.cg.shared.global [%0], [%1], 16;"
                     :: "r"(dst), "l"(T16 + (size_t)r * 32 + c * 4));
    }
    asm volatile("cp.async.commit_group;" ::: "memory");
    if (tid < 64) biasf[tid] = (mb[tid] == 0) ? -3000.f : 0.f;

    float rs0 = 0.f, rs1 = 0.f;
    float oacc[4][2][4];
#pragma unroll
    for (int me = 0; me < 4; me++)
#pragma unroll
        for (int n = 0; n < 2; n++)
#pragma unroll
            for (int r = 0; r < 4; r++) oacc[me][n][r] = 0.f;

    const uint32_t qro = (uint32_t)((w16 + l7 + r8) * 144 + r16 * 2);
    const uint32_t kro = (uint32_t)((l7 + r16) * 144 + r8 * 2);

#pragma unroll 1
    for (int i = 0; i < NIT; i++) {
        asm volatile("cp.async.wait_group 0;" ::: "memory");
        __syncthreads();

        if (i + 1 < NIT) {
            int j0 = (i + 1) * KT;
            uint32_t kst = A_KV + ((i + 1) & 1) * A_KVST;
#pragma unroll
            for (int it = 0; it < 2; it++) {
                int f = tid + it * 256;
                int r = f >> 3, c = f & 7;
                uint32_t dst = smb + kst + (uint32_t)(r * 144 + c * 16);
                asm volatile("cp.async.cg.shared.global [%0], [%1], 16;"
                             :: "r"(dst), "l"(T16 + (size_t)(j0 + r) * 32 + c * 4));
            }
            asm volatile("cp.async.commit_group;" ::: "memory");
            if (tid < 64)
                biasf[((i + 1) & 1) * 64 + tid] =
                    (mb[j0 + tid] == 0) ? -3000.f : 0.f;
        }

        const uint32_t kvb = smb + A_KV + (i & 1) * A_KVST;

        // ---- S = Q K^T (fp16): 16q x 64key ----
        float sacc[8][4];
#pragma unroll
        for (int kg = 0; kg < 8; kg++)
#pragma unroll
            for (int r = 0; r < 4; r++) sacc[kg][r] = 0.f;

#pragma unroll
        for (int kb = 0; kb < 4; kb++) {
            uint32_t qf[4];
            ldsm4(qf, smb + A_Q + qro + kb * 32);
#pragma unroll
            for (int kt = 0; kt < 4; kt++) {
                uint32_t kf[4];
                ldsm4(kf, kvb + (uint32_t)(kt * 16 * 144) + kro + kb * 32);
                mma16h(sacc[kt * 2],     qf, kf);
                mma16h(sacc[kt * 2 + 1], qf, kf + 2);
            }
        }

        // ---- exp via MUFU ex2 -> packed fp16 PV B-frags ----
        uint32_t u01[8], u23[8];
        const float* bi = biasf + (i & 1) * 64;
#pragma unroll
        for (int kg = 0; kg < 8; kg++) {
            float bx = bi[kg * 8 + 2 * t4];
            float by = bi[kg * 8 + 2 * t4 + 1];
            float* c = sacc[kg];
            float p0 = ex2(fmaf(c[0], CE, bx));
            float p1 = ex2(fmaf(c[1], CE, by));
            float p2 = ex2(fmaf(c[2], CE, bx));
            float p3 = ex2(fmaf(c[3], CE, by));
            rs0 += p0 + p1;
            rs1 += p2 + p3;
            u01[kg] = packf16(p0, p1);
            u23[kg] = packf16(p2, p3);
        }

        // ---- O^T += V^T P^T (V tile == KV tile) ----
#pragma unroll
        for (int kt = 0; kt < 4; kt++) {
            uint32_t b0[2] = { u01[kt * 2], u01[kt * 2 + 1] };
            uint32_t b1[2] = { u23[kt * 2], u23[kt * 2 + 1] };
#pragma unroll
            for (int me = 0; me < 4; me++) {
                uint32_t ah[4];
                ldsm4t(ah, kvb + (uint32_t)((kt * 16 + l7 + r16) * 144
                                            + (me * 16 + r8) * 2));
                mma16h(oacc[me][0], ah, b0);
                mma16h(oacc[me][1], ah, b1);
            }
        }
    }

    // ---- epilogue ----
    rs0 += __shfl_xor_sync(0xffffffffu, rs0, 1);
    rs0 += __shfl_xor_sync(0xffffffffu, rs0, 2);
    rs1 += __shfl_xor_sync(0xffffffffu, rs1, 1);
    rs1 += __shfl_xor_sync(0xffffffffu, rs1, 2);
    float* lred = (float*)(smem + A_OL);
    if (t4 == 0) {
        lred[w16 + g] = rs0;
        lred[w16 + 8 + g] = rs1;
    }
    __syncthreads();

    const int qa = w16 + 2 * t4;
    const float inv0 = 1.f / lred[qa];
    const float inv1 = 1.f / lred[qa + 1];
    const float inv2 = 1.f / lred[qa + 8];
    const float inv3 = 1.f / lred[qa + 9];
    float* ob = out + ((size_t)b * NSEQ + q0 + qa) * (NH * HD) + h * HD;
#pragma unroll
    for (int me = 0; me < 4; me++) {
        int e0 = me * 16 + g;
        ob[e0]                   = oacc[me][0][0] * inv0;
        ob[NH * HD + e0]         = oacc[me][0][1] * inv1;
        ob[e0 + 8]               = oacc[me][0][2] * inv0;
        ob[NH * HD + e0 + 8]     = oacc[me][0][3] * inv1;
        ob[8 * NH * HD + e0]     = oacc[me][1][0] * inv2;
        ob[9 * NH * HD + e0]     = oacc[me][1][1] * inv3;
        ob[8 * NH * HD + e0 + 8] = oacc[me][1][2] * inv2;
        ob[9 * NH * HD + e0 + 8] = oacc[me][1][3] * inv3;
    }
}

// ---------------------------------------------------------------------------
extern "C" void kernel_launch(void* const* d_in, const int* in_sizes, int n_in,
                              void* d_out, int out_size) {
    const float* hidden = (const float*)d_in[0];
    const int*   amask  = (const int*)d_in[1];
    const float* Wt     = (const float*)d_in[2];
    const float* Wa     = (const float*)d_in[3];
    float* out = (float*)d_out;

    k_pre<<<WC_BLKS + CVT_BLKS, 256>>>(hidden, Wt, Wa);

    cudaFuncSetAttribute(k_proj_mma, cudaFuncAttributeMaxDynamicSharedMemorySize,
                         PROJ_SMEM_BYTES);
    k_proj_mma<<<dim3(NSEQ / 128, NB * NH), 256, PROJ_SMEM_BYTES>>>(0);

    cudaFuncSetAttribute(k_attn7, cudaFuncAttributeMaxDynamicSharedMemorySize,
                         A_SM);
    k_attn7<<<dim3(NSEQ / QT, NB * NH), 256, A_SM>>>(amask, out);
}

// round 15
// speedup vs baseline: 1.4572x; 1.0339x over previous
#include <cuda_runtime.h>
#include <cuda_bf16.h>
#include <cuda_fp16.h>
#include <cstdint>

#define NB    8
#define NSEQ  1024
#define HIDD  768
#define NH    12
#define LR    256
#define HD    64

#define QT    128
#define KT    64
#define NIT   (NSEQ / KT)

// scratch (no cudaMalloc allowed)
__device__ uint32_t g_Xh[NB * NSEQ * (HIDD / 2)];    // X bf16 hi, k-pair packed
__device__ uint32_t g_Xl[NB * NSEQ * (HIDD / 2)];
__device__ uint32_t g_Wh[NH * HD * (HIDD / 2)];      // Wc bf16 hi
__device__ uint32_t g_Wl[NH * HD * (HIDD / 2)];
__device__ uint32_t g_t16[NB * NH * NSEQ * (HD / 2)];// t fp16 e-pairs (q=k=v)

// ---------------------------------------------------------------------------
// helpers
// ---------------------------------------------------------------------------
__device__ __forceinline__ uint32_t smem_u32(const void* p) {
    uint32_t a;
    asm("{ .reg .u64 t; cvta.to.shared.u64 t, %1; cvt.u32.u64 %0, t; }"
        : "=r"(a) : "l"(p));
    return a;
}
__device__ __forceinline__ uint32_t packbf(float lo, float hi) {
    uint32_t r;
    asm("cvt.rn.bf16x2.f32 %0, %1, %2;" : "=r"(r) : "f"(hi), "f"(lo));
    return r;
}
__device__ __forceinline__ uint32_t packf16(float lo, float hi) {
    uint32_t r;
    asm("cvt.rn.f16x2.f32 %0, %1, %2;" : "=r"(r) : "f"(hi), "f"(lo));
    return r;
}
__device__ __forceinline__ void split2(float x0, float x1,
                                       uint32_t& hp, uint32_t& lp) {
    hp = packbf(x0, x1);
    float h0 = __uint_as_float(hp << 16);
    float h1 = __uint_as_float(hp & 0xffff0000u);
    lp = packbf(x0 - h0, x1 - h1);
}
// fp16x2 exp2 on MUFU (one op for two lanes)
__device__ __forceinline__ uint32_t ex2h2(uint32_t x) {
    uint32_t r; asm("ex2.approx.f16x2 %0, %1;" : "=r"(r) : "r"(x)); return r;
}
__device__ __forceinline__ uint32_t hadd2u(uint32_t a, uint32_t b) {
    uint32_t r; asm("add.rn.f16x2 %0, %1, %2;" : "=r"(r) : "r"(a), "r"(b));
    return r;
}
// bf16 m16n8k16 (projection)
__device__ __forceinline__ void mma16(float* c, const uint32_t* a, const uint32_t* b) {
    asm volatile(
        "mma.sync.aligned.m16n8k16.row.col.f32.bf16.bf16.f32 "
        "{%0,%1,%2,%3}, {%4,%5,%6,%7}, {%8,%9}, {%0,%1,%2,%3};"
        : "+f"(c[0]), "+f"(c[1]), "+f"(c[2]), "+f"(c[3])
        : "r"(a[0]), "r"(a[1]), "r"(a[2]), "r"(a[3]), "r"(b[0]), "r"(b[1]));
}
// fp16 m16n8k16 (attention S and PV)
__device__ __forceinline__ void mma16h(float* c, const uint32_t* a, const uint32_t* b) {
    asm volatile(
        "mma.sync.aligned.m16n8k16.row.col.f32.f16.f16.f32 "
        "{%0,%1,%2,%3}, {%4,%5,%6,%7}, {%8,%9}, {%0,%1,%2,%3};"
        : "+f"(c[0]), "+f"(c[1]), "+f"(c[2]), "+f"(c[3])
        : "r"(a[0]), "r"(a[1]), "r"(a[2]), "r"(a[3]), "r"(b[0]), "r"(b[1]));
}
__device__ __forceinline__ void ldsm4(uint32_t* r, uint32_t a) {
    asm volatile("ldmatrix.sync.aligned.m8n8.x4.b16 {%0,%1,%2,%3}, [%4];"
        : "=r"(r[0]), "=r"(r[1]), "=r"(r[2]), "=r"(r[3]) : "r"(a));
}
__device__ __forceinline__ void ldsm4t(uint32_t* r, uint32_t a) {
    asm volatile("ldmatrix.sync.aligned.m8n8.x4.trans.b16 {%0,%1,%2,%3}, [%4];"
        : "=r"(r[0]), "=r"(r[1]), "=r"(r[2]), "=r"(r[3]) : "r"(a));
}

// ---------------------------------------------------------------------------
// Kernel 0 (merged): blocks [0,288): Wc = Wa@Wt (fp32) -> bf16 h/l, d-chunk 32
//   blocks [288, 288+1536): split X -> bf16 h/l (16 floats/thread)
// ---------------------------------------------------------------------------
#define WC_BLKS  (NH * 24)                   // 288
#define CVT_BLKS (NB * NSEQ * HIDD / 4096)   // 1536

__global__ __launch_bounds__(256) void k_pre(const float* __restrict__ X,
                                             const float* __restrict__ Wt,
                                             const float* __restrict__ Wa) {
    const int tid = threadIdx.x;
    if (blockIdx.x >= WC_BLKS) {
        size_t t = (size_t)(blockIdx.x - WC_BLKS) * 256 + tid;
        float4 v[4];
#pragma unroll
        for (int i = 0; i < 4; i++) v[i] = *(const float4*)&X[t * 16 + i * 4];
        uint4 hp[2], lp[2];
#pragma unroll
        for (int i = 0; i < 2; i++) {
            split2(v[i * 2].x, v[i * 2].y, hp[i].x, lp[i].x);
            split2(v[i * 2].z, v[i * 2].w, hp[i].y, lp[i].y);
            split2(v[i * 2 + 1].x, v[i * 2 + 1].y, hp[i].z, lp[i].z);
            split2(v[i * 2 + 1].z, v[i * 2 + 1].w, hp[i].w, lp[i].w);
        }
        *(uint4*)&g_Xh[t * 8]     = hp[0];
        *(uint4*)&g_Xh[t * 8 + 4] = hp[1];
        *(uint4*)&g_Xl[t * 8]     = lp[0];
        *(uint4*)&g_Xl[t * 8 + 4] = lp[1];
        return;
    }
    // ---- Wc GEMM: head h, d-chunk of 32 ----
    const int h  = blockIdx.x / 24;
    const int d0 = (blockIdx.x % 24) * 32;
    __shared__ float Wa_s[64 * 36];
    __shared__ float Wt_s[32 * 36];

    const int te = tid / 8;    // 0..31, 2 e-rows each
    const int td = tid % 8;    // 4 d-cols each

    float acc[2][4];
#pragma unroll
    for (int i = 0; i < 2; i++)
#pragma unroll
        for (int j = 0; j < 4; j++) acc[i][j] = 0.f;

    for (int l0 = 0; l0 < LR; l0 += 32) {
#pragma unroll
        for (int it = 0; it < 2; it++) {
            int f = tid + it * 256;
            int e = f / 8, l4 = f % 8;
            float4 v = *(const float4*)&Wa[((size_t)h * 64 + e) * LR + l0 + l4 * 4];
            *(float4*)&Wa_s[e * 36 + l4 * 4] = v;
        }
        {
            int l = tid / 8, c4 = tid % 8;
            float4 v = *(const float4*)&Wt[((size_t)h * LR + l0 + l) * HIDD + d0 + c4 * 4];
            *(float4*)&Wt_s[l * 36 + c4 * 4] = v;
        }
        __syncthreads();
#pragma unroll
        for (int l = 0; l < 32; l++) {
            float a0 = Wa_s[(te * 2) * 36 + l];
            float a1 = Wa_s[(te * 2 + 1) * 36 + l];
            float w[4];
            *(float4*)w = *(const float4*)&Wt_s[l * 36 + td * 4];
#pragma unroll
            for (int j = 0; j < 4; j++) {
                acc[0][j] = fmaf(a0, w[j], acc[0][j]);
                acc[1][j] = fmaf(a1, w[j], acc[1][j]);
            }
        }
        __syncthreads();
    }
#pragma unroll
    for (int i = 0; i < 2; i++) {
        const int e = te * 2 + i;
        uint32_t h0, l0u, h1, l1u;
        split2(acc[i][0], acc[i][1], h0, l0u);
        split2(acc[i][2], acc[i][3], h1, l1u);
        size_t base = ((size_t)h * HD + e) * (HIDD / 2) + d0 / 2 + td * 2;
        *(uint2*)&g_Wh[base] = make_uint2(h0, h1);
        *(uint2*)&g_Wl[base] = make_uint2(l0u, l1u);
    }
}

// ---------------------------------------------------------------------------
// Kernel 1: t = X * Wc^T, 3-term bf16 split, ldmatrix frags, single-sync loop.
// ---------------------------------------------------------------------------
#define PJ_X    0                      // per stage: Xh 128*80, Xl at +10240
#define PJ_XST  20480
#define PJ_W    40960                  // per stage: Wh 64*80, Wl at +5120
#define PJ_WST  10240
#define PROJ_SMEM_BYTES 61440
#define NKIT  (HIDD / 32)              // 24

__global__ __launch_bounds__(256, 2) void k_proj_mma(int dummy) {
    extern __shared__ __align__(128) char smem[];
    const uint32_t smb = smem_u32(smem);

    const int bh = blockIdx.y, b = bh / NH, h = bh % NH;
    const int n0 = blockIdx.x * 128;
    const int tid = threadIdx.x, wid = tid >> 5, lid = tid & 31;
    const int mw = wid & 3, nw = wid >> 2;
    const int g = lid >> 2, t4 = lid & 3;
    const int mrow = mw * 32, ncol = nw * 32;
    const int l7 = lid & 7;
    const int r8  = (lid & 8)  ? 8 : 0;
    const int r16 = (lid & 16) ? 8 : 0;

    const uint32_t* Xh = g_Xh + (size_t)(b * NSEQ + n0) * (HIDD / 2);
    const uint32_t* Xl = g_Xl + (size_t)(b * NSEQ + n0) * (HIDD / 2);
    const uint32_t* Wh = g_Wh + (size_t)h * HD * (HIDD / 2);
    const uint32_t* Wl = g_Wl + (size_t)h * HD * (HIDD / 2);

    auto issue = [&](int ki) {
        const uint32_t xb = smb + PJ_X + (ki & 1) * PJ_XST;
        const uint32_t wb = smb + PJ_W + (ki & 1) * PJ_WST;
        const int k4 = ki * 16;
#pragma unroll
        for (int it = 0; it < 2; it++) {
            int f = tid + it * 256;
            int r = f >> 2, c = f & 3;
            uint32_t d = (uint32_t)(r * 80 + c * 16);
            asm volatile("cp.async.cg.shared.global [%0], [%1], 16;"
                         :: "r"(xb + d), "l"(Xh + (size_t)r * 384 + k4 + c * 4));
            asm volatile("cp.async.cg.shared.global [%0], [%1], 16;"
                         :: "r"(xb + 10240 + d), "l"(Xl + (size_t)r * 384 + k4 + c * 4));
        }
        {
            int r = tid >> 2, c = tid & 3;
            uint32_t d = (uint32_t)(r * 80 + c * 16);
            asm volatile("cp.async.cg.shared.global [%0], [%1], 16;"
                         :: "r"(wb + d), "l"(Wh + (size_t)r * 384 + k4 + c * 4));
            asm volatile("cp.async.cg.shared.global [%0], [%1], 16;"
                         :: "r"(wb + 5120 + d), "l"(Wl + (size_t)r * 384 + k4 + c * 4));
        }
        asm volatile("cp.async.commit_group;" ::: "memory");
    };

    float acc[2][4][4];
#pragma unroll
    for (int mi = 0; mi < 2; mi++)
#pragma unroll
        for (int nj = 0; nj < 4; nj++)
#pragma unroll
            for (int r = 0; r < 4; r++) acc[mi][nj][r] = 0.f;

    const uint32_t aro = (uint32_t)((mrow + l7 + r8) * 80 + r16 * 2);
    const uint32_t bro = (uint32_t)((ncol + l7 + r16) * 80 + r8 * 2);

    issue(0);
#pragma unroll 1
    for (int ki = 0; ki < NKIT; ki++) {
        asm volatile("cp.async.wait_group 0;" ::: "memory");
        __syncthreads();
        if (ki + 1 < NKIT) issue(ki + 1);

        const uint32_t xb = smb + PJ_X + (ki & 1) * PJ_XST;
        const uint32_t wb = smb + PJ_W + (ki & 1) * PJ_WST;
#pragma unroll
        for (int c16 = 0; c16 < 2; c16++) {
            const uint32_t off = c16 * 32;
            uint32_t xh0[4], xh1[4], xl0[4], xl1[4];
            ldsm4(xh0, xb + aro + off);
            ldsm4(xh1, xb + aro + 16 * 80 + off);
            ldsm4(xl0, xb + 10240 + aro + off);
            ldsm4(xl1, xb + 10240 + aro + 16 * 80 + off);
            uint32_t wh0[4], wh1[4], wl0[4], wl1[4];
            ldsm4(wh0, wb + bro + off);
            ldsm4(wh1, wb + bro + 16 * 80 + off);
            ldsm4(wl0, wb + 5120 + bro + off);
            ldsm4(wl1, wb + 5120 + bro + 16 * 80 + off);
            mma16(acc[0][0], xh0, wh0);     mma16(acc[0][0], xh0, wl0);
            mma16(acc[0][0], xl0, wh0);
            mma16(acc[0][1], xh0, wh0 + 2); mma16(acc[0][1], xh0, wl0 + 2);
            mma16(acc[0][1], xl0, wh0 + 2);
            mma16(acc[0][2], xh0, wh1);     mma16(acc[0][2], xh0, wl1);
            mma16(acc[0][2], xl0, wh1);
            mma16(acc[0][3], xh0, wh1 + 2); mma16(acc[0][3], xh0, wl1 + 2);
            mma16(acc[0][3], xl0, wh1 + 2);
            mma16(acc[1][0], xh1, wh0);     mma16(acc[1][0], xh1, wl0);
            mma16(acc[1][0], xl1, wh0);
            mma16(acc[1][1], xh1, wh0 + 2); mma16(acc[1][1], xh1, wl0 + 2);
            mma16(acc[1][1], xl1, wh0 + 2);
            mma16(acc[1][2], xh1, wh1);     mma16(acc[1][2], xh1, wl1);
            mma16(acc[1][2], xl1, wh1);
            mma16(acc[1][3], xh1, wh1 + 2); mma16(acc[1][3], xh1, wl1 + 2);
            mma16(acc[1][3], xl1, wh1 + 2);
        }
    }

    // epilogue: fp16 t
    uint32_t* T16 = g_t16 + ((size_t)bh * NSEQ + n0) * (HD / 2);
#pragma unroll
    for (int mi = 0; mi < 2; mi++) {
        int r0 = mrow + mi * 16 + g;
#pragma unroll
        for (int nj = 0; nj < 4; nj++) {
            int cu = (ncol + nj * 8) / 2 + t4;
            T16[(size_t)r0 * (HD / 2) + cu] =
                packf16(acc[mi][nj][0], acc[mi][nj][1]);
            T16[(size_t)(r0 + 8) * (HD / 2) + cu] =
                packf16(acc[mi][nj][2], acc[mi][nj][3]);
        }
    }
}

// ---------------------------------------------------------------------------
// Kernel 2: all-fp16 flash attention; exp via ex2.approx.f16x2 (half MUFU ops,
// output is directly the packed PV B-frag; row sums via f16x2 adds per iter).
// ---------------------------------------------------------------------------
#define A_Q    0                    // 128 * 144 fp16
#define A_KV   18432                // 2 stages * 64*144
#define A_KVST 9216
#define A_OB   36864                // float[2][64]
#define A_OL   37376                // float[128]
#define A_SM   37888

#define CE 0.052058774f             // 768^-0.5 * log2(e)

__global__ __launch_bounds__(256, 2) void k_attn7(const int* __restrict__ amask,
                                                  float* __restrict__ out) {
    extern __shared__ __align__(128) char smem[];
    const uint32_t smb = smem_u32(smem);

    const int bh = blockIdx.y, b = bh / NH, h = bh % NH;
    const int q0 = blockIdx.x * QT;
    const int tid = threadIdx.x, wid = tid >> 5, lid = tid & 31;
    const int g = lid >> 2, t4 = lid & 3;
    const int w16 = wid * 16;
    const int l7 = lid & 7;
    const int r8  = (lid & 8)  ? 8 : 0;
    const int r16 = (lid & 16) ? 8 : 0;

    const uint32_t* T16 = g_t16 + (size_t)bh * NSEQ * (HD / 2);
    const int* mb = amask + (size_t)b * NSEQ;
    float* biasf = (float*)(smem + A_OB);

    // prologue: Q fp16, KV tile 0, bias 0
#pragma unroll
    for (int it = 0; it < 4; it++) {
        int f = tid + it * 256;
        int r = f >> 3, c = f & 7;
        uint32_t dst = smb + A_Q + (uint32_t)(r * 144 + c * 16);
        asm volatile("cp.async.cg.shared.global [%0], [%1], 16;"
                     :: "r"(dst), "l"(T16 + (size_t)(q0 + r) * 32 + c * 4));
    }
#pragma unroll
    for (int it = 0; it < 2; it++) {
        int f = tid + it * 256;
        int r = f >> 3, c = f & 7;
        uint32_t dst = smb + A_KV + (uint32_t)(r * 144 + c * 16);
        asm volatile("cp.async.cg.shared.global [%0], [%1], 16;"
                     :: "r"(dst), "l"(T16 + (size_t)r * 32 + c * 4));
    }
    asm volatile("cp.async.commit_group;" ::: "memory");
    if (tid < 64) biasf[tid] = (mb[tid] == 0) ? -3000.f : 0.f;

    float rs0 = 0.f, rs1 = 0.f;
    float oacc[4][2][4];
#pragma unroll
    for (int me = 0; me < 4; me++)
#pragma unroll
        for (int n = 0; n < 2; n++)
#pragma unroll
            for (int r = 0; r < 4; r++) oacc[me][n][r] = 0.f;

    const uint32_t qro = (uint32_t)((w16 + l7 + r8) * 144 + r16 * 2);
    const uint32_t kro = (uint32_t)((l7 + r16) * 144 + r8 * 2);

#pragma unroll 1
    for (int i = 0; i < NIT; i++) {
        asm volatile("cp.async.wait_group 0;" ::: "memory");
        __syncthreads();

        if (i + 1 < NIT) {
            int j0 = (i + 1) * KT;
            uint32_t kst = A_KV + ((i + 1) & 1) * A_KVST;
#pragma unroll
            for (int it = 0; it < 2; it++) {
                int f = tid + it * 256;
                int r = f >> 3, c = f & 7;
                uint32_t dst = smb + kst + (uint32_t)(r * 144 + c * 16);
                asm volatile("cp.async.cg.shared.global [%0], [%1], 16;"
                             :: "r"(dst), "l"(T16 + (size_t)(j0 + r) * 32 + c * 4));
            }
            asm volatile("cp.async.commit_group;" ::: "memory");
            if (tid < 64)
                biasf[((i + 1) & 1) * 64 + tid] =
                    (mb[j0 + tid] == 0) ? -3000.f : 0.f;
        }

        const uint32_t kvb = smb + A_KV + (i & 1) * A_KVST;

        // ---- S = Q K^T (fp16): 16q x 64key ----
        float sacc[8][4];
#pragma unroll
        for (int kg = 0; kg < 8; kg++)
#pragma unroll
            for (int r = 0; r < 4; r++) sacc[kg][r] = 0.f;

#pragma unroll
        for (int kb = 0; kb < 4; kb++) {
            uint32_t qf[4];
            ldsm4(qf, smb + A_Q + qro + kb * 32);
#pragma unroll
            for (int kt = 0; kt < 4; kt++) {
                uint32_t kf[4];
                ldsm4(kf, kvb + (uint32_t)(kt * 16 * 144) + kro + kb * 32);
                mma16h(sacc[kt * 2],     qf, kf);
                mma16h(sacc[kt * 2 + 1], qf, kf + 2);
            }
        }

        // ---- exp via ex2.approx.f16x2 -> packed fp16 PV B-frags ----
        uint32_t u01[8], u23[8];
        uint32_t hs0 = 0u, hs1 = 0u;     // f16x2 partial row sums
        const float* bi = biasf + (i & 1) * 64;
#pragma unroll
        for (int kg = 0; kg < 8; kg++) {
            float bx = bi[kg * 8 + 2 * t4];
            float by = bi[kg * 8 + 2 * t4 + 1];
            float* c = sacc[kg];
            uint32_t e01 = packf16(fmaf(c[0], CE, bx), fmaf(c[1], CE, by));
            uint32_t e23 = packf16(fmaf(c[2], CE, bx), fmaf(c[3], CE, by));
            u01[kg] = ex2h2(e01);
            u23[kg] = ex2h2(e23);
            hs0 = hadd2u(hs0, u01[kg]);
            hs1 = hadd2u(hs1, u23[kg]);
        }
        {
            __half2 h0 = *reinterpret_cast<__half2*>(&hs0);
            __half2 h1 = *reinterpret_cast<__half2*>(&hs1);
            rs0 += __low2float(h0) + __high2float(h0);
            rs1 += __low2float(h1) + __high2float(h1);
        }

        // ---- O^T += V^T P^T (V tile == KV tile) ----
#pragma unroll
        for (int kt = 0; kt < 4; kt++) {
            uint32_t b0[2] = { u01[kt * 2], u01[kt * 2 + 1] };
            uint32_t b1[2] = { u23[kt * 2], u23[kt * 2 + 1] };
#pragma unroll
            for (int me = 0; me < 4; me++) {
                uint32_t ah[4];
                ldsm4t(ah, kvb + (uint32_t)((kt * 16 + l7 + r16) * 144
                                            + (me * 16 + r8) * 2));
                mma16h(oacc[me][0], ah, b0);
                mma16h(oacc[me][1], ah, b1);
            }
        }
    }

    // ---- epilogue ----
    rs0 += __shfl_xor_sync(0xffffffffu, rs0, 1);
    rs0 += __shfl_xor_sync(0xffffffffu, rs0, 2);
    rs1 += __shfl_xor_sync(0xffffffffu, rs1, 1);
    rs1 += __shfl_xor_sync(0xffffffffu, rs1, 2);
    float* lred = (float*)(smem + A_OL);
    if (t4 == 0) {
        lred[w16 + g] = rs0;
        lred[w16 + 8 + g] = rs1;
    }
    __syncthreads();

    const int qa = w16 + 2 * t4;
    const float inv0 = 1.f / lred[qa];
    const float inv1 = 1.f / lred[qa + 1];
    const float inv2 = 1.f / lred[qa + 8];
    const float inv3 = 1.f / lred[qa + 9];
    float* ob = out + ((size_t)b * NSEQ + q0 + qa) * (NH * HD) + h * HD;
#pragma unroll
    for (int me = 0; me < 4; me++) {
        int e0 = me * 16 + g;
        ob[e0]                   = oacc[me][0][0] * inv0;
        ob[NH * HD + e0]         = oacc[me][0][1] * inv1;
        ob[e0 + 8]               = oacc[me][0][2] * inv0;
        ob[NH * HD + e0 + 8]     = oacc[me][0][3] * inv1;
        ob[8 * NH * HD + e0]     = oacc[me][1][0] * inv2;
        ob[9 * NH * HD + e0]     = oacc[me][1][1] * inv3;
        ob[8 * NH * HD + e0 + 8] = oacc[me][1][2] * inv2;
        ob[9 * NH * HD + e0 + 8] = oacc[me][1][3] * inv3;
    }
}

// ---------------------------------------------------------------------------
extern "C" void kernel_launch(void* const* d_in, const int* in_sizes, int n_in,
                              void* d_out, int out_size) {
    const float* hidden = (const float*)d_in[0];
    const int*   amask  = (const int*)d_in[1];
    const float* Wt     = (const float*)d_in[2];
    const float* Wa     = (const float*)d_in[3];
    float* out = (float*)d_out;

    k_pre<<<WC_BLKS + CVT_BLKS, 256>>>(hidden, Wt, Wa);

    cudaFuncSetAttribute(k_proj_mma, cudaFuncAttributeMaxDynamicSharedMemorySize,
                         PROJ_SMEM_BYTES);
    k_proj_mma<<<dim3(NSEQ / 128, NB * NH), 256, PROJ_SMEM_BYTES>>>(0);

    cudaFuncSetAttribute(k_attn7, cudaFuncAttributeMaxDynamicSharedMemorySize,
                         A_SM);
    k_attn7<<<dim3(NSEQ / QT, NB * NH), 256, A_SM>>>(amask, out);
}

// round 16
// speedup vs baseline: 1.4891x; 1.0219x over previous
#include <cuda_runtime.h>
#include <cuda_bf16.h>
#include <cuda_fp16.h>
#include <cstdint>

#define NB    8
#define NSEQ  1024
#define HIDD  768
#define NH    12
#define LR    256
#define HD    64

#define QT    128
#define KT    64
#define NIT   (NSEQ / KT)

// scratch (no cudaMalloc allowed)
__device__ uint32_t g_Wh[NH * HD * (HIDD / 2)];      // Wc bf16 hi, k-pair packed
__device__ uint32_t g_Wl[NH * HD * (HIDD / 2)];      // Wc bf16 lo
__device__ uint32_t g_t16[NB * NH * NSEQ * (HD / 2)];// t fp16 e-pairs (q=k=v)

// ---------------------------------------------------------------------------
// helpers
// ---------------------------------------------------------------------------
__device__ __forceinline__ uint32_t smem_u32(const void* p) {
    uint32_t a;
    asm("{ .reg .u64 t; cvta.to.shared.u64 t, %1; cvt.u32.u64 %0, t; }"
        : "=r"(a) : "l"(p));
    return a;
}
__device__ __forceinline__ uint32_t packbf(float lo, float hi) {
    uint32_t r;
    asm("cvt.rn.bf16x2.f32 %0, %1, %2;" : "=r"(r) : "f"(hi), "f"(lo));
    return r;
}
__device__ __forceinline__ uint32_t packf16(float lo, float hi) {
    uint32_t r;
    asm("cvt.rn.f16x2.f32 %0, %1, %2;" : "=r"(r) : "f"(hi), "f"(lo));
    return r;
}
__device__ __forceinline__ void split2(float x0, float x1,
                                       uint32_t& hp, uint32_t& lp) {
    hp = packbf(x0, x1);
    float h0 = __uint_as_float(hp << 16);
    float h1 = __uint_as_float(hp & 0xffff0000u);
    lp = packbf(x0 - h0, x1 - h1);
}
__device__ __forceinline__ uint32_t ex2h2(uint32_t x) {
    uint32_t r; asm("ex2.approx.f16x2 %0, %1;" : "=r"(r) : "r"(x)); return r;
}
__device__ __forceinline__ uint32_t hadd2u(uint32_t a, uint32_t b) {
    uint32_t r; asm("add.rn.f16x2 %0, %1, %2;" : "=r"(r) : "r"(a), "r"(b));
    return r;
}
// bf16 m16n8k16 (projection)
__device__ __forceinline__ void mma16(float* c, const uint32_t* a, const uint32_t* b) {
    asm volatile(
        "mma.sync.aligned.m16n8k16.row.col.f32.bf16.bf16.f32 "
        "{%0,%1,%2,%3}, {%4,%5,%6,%7}, {%8,%9}, {%0,%1,%2,%3};"
        : "+f"(c[0]), "+f"(c[1]), "+f"(c[2]), "+f"(c[3])
        : "r"(a[0]), "r"(a[1]), "r"(a[2]), "r"(a[3]), "r"(b[0]), "r"(b[1]));
}
// fp16 m16n8k16 (attention S and PV)
__device__ __forceinline__ void mma16h(float* c, const uint32_t* a, const uint32_t* b) {
    asm volatile(
        "mma.sync.aligned.m16n8k16.row.col.f32.f16.f16.f32 "
        "{%0,%1,%2,%3}, {%4,%5,%6,%7}, {%8,%9}, {%0,%1,%2,%3};"
        : "+f"(c[0]), "+f"(c[1]), "+f"(c[2]), "+f"(c[3])
        : "r"(a[0]), "r"(a[1]), "r"(a[2]), "r"(a[3]), "r"(b[0]), "r"(b[1]));
}
__device__ __forceinline__ void ldsm4(uint32_t* r, uint32_t a) {
    asm volatile("ldmatrix.sync.aligned.m8n8.x4.b16 {%0,%1,%2,%3}, [%4];"
        : "=r"(r[0]), "=r"(r[1]), "=r"(r[2]), "=r"(r[3]) : "r"(a));
}
__device__ __forceinline__ void ldsm4t(uint32_t* r, uint32_t a) {
    asm volatile("ldmatrix.sync.aligned.m8n8.x4.trans.b16 {%0,%1,%2,%3}, [%4];"
        : "=r"(r[0]), "=r"(r[1]), "=r"(r[2]), "=r"(r[3]) : "r"(a));
}

// ---------------------------------------------------------------------------
// Kernel 0: Wc = Wa@Wt (fp32 exact) -> bf16 h/l, d-chunk 32 (288 blocks)
// ---------------------------------------------------------------------------
#define WC_BLKS (NH * 24)

__global__ __launch_bounds__(256) void k_pre(const float* __restrict__ Wt,
                                             const float* __restrict__ Wa) {
    const int tid = threadIdx.x;
    const int h  = blockIdx.x / 24;
    const int d0 = (blockIdx.x % 24) * 32;
    __shared__ float Wa_s[64 * 36];
    __shared__ float Wt_s[32 * 36];

    const int te = tid / 8;    // 0..31, 2 e-rows each
    const int td = tid % 8;    // 4 d-cols each

    float acc[2][4];
#pragma unroll
    for (int i = 0; i < 2; i++)
#pragma unroll
        for (int j = 0; j < 4; j++) acc[i][j] = 0.f;

    for (int l0 = 0; l0 < LR; l0 += 32) {
#pragma unroll
        for (int it = 0; it < 2; it++) {
            int f = tid + it * 256;
            int e = f / 8, l4 = f % 8;
            float4 v = *(const float4*)&Wa[((size_t)h * 64 + e) * LR + l0 + l4 * 4];
            *(float4*)&Wa_s[e * 36 + l4 * 4] = v;
        }
        {
            int l = tid / 8, c4 = tid % 8;
            float4 v = *(const float4*)&Wt[((size_t)h * LR + l0 + l) * HIDD + d0 + c4 * 4];
            *(float4*)&Wt_s[l * 36 + c4 * 4] = v;
        }
        __syncthreads();
#pragma unroll
        for (int l = 0; l < 32; l++) {
            float a0 = Wa_s[(te * 2) * 36 + l];
            float a1 = Wa_s[(te * 2 + 1) * 36 + l];
            float w[4];
            *(float4*)w = *(const float4*)&Wt_s[l * 36 + td * 4];
#pragma unroll
            for (int j = 0; j < 4; j++) {
                acc[0][j] = fmaf(a0, w[j], acc[0][j]);
                acc[1][j] = fmaf(a1, w[j], acc[1][j]);
            }
        }
        __syncthreads();
    }
#pragma unroll
    for (int i = 0; i < 2; i++) {
        const int e = te * 2 + i;
        uint32_t h0, l0u, h1, l1u;
        split2(acc[i][0], acc[i][1], h0, l0u);
        split2(acc[i][2], acc[i][3], h1, l1u);
        size_t base = ((size_t)h * HD + e) * (HIDD / 2) + d0 / 2 + td * 2;
        *(uint2*)&g_Wh[base] = make_uint2(h0, h1);
        *(uint2*)&g_Wl[base] = make_uint2(l0u, l1u);
    }
}

// ---------------------------------------------------------------------------
// Kernel 1: t = X * Wc^T, 3-term bf16 split. X loaded as fp32 and split to
// bf16 h/l IN-KERNEL (hidden under the MMA shadow) — no g_Xh/g_Xl round-trip.
// CTA: 128 n x 64 e of one (b,h); 8 warps (4m x 2n); K-tile 32, 2-stage XF/W,
// single-buffered converted Xh/Xl (top-of-loop sync orders reuse).
// ---------------------------------------------------------------------------
#define PJ_XF   0                      // 2 stages * 128*144 (fp32 X tile)
#define PJ_XFST 18432
#define PJ_XH   36864                  // 128*80  (converted bf16 hi, single)
#define PJ_XL   47104                  // 128*80  (converted bf16 lo, single)
#define PJ_W    57344                  // 2 stages * (Wh 64*80 | Wl +5120)
#define PJ_WST  10240
#define PROJ_SMEM_BYTES 77824
#define NKIT  (HIDD / 32)              // 24

__global__ __launch_bounds__(256, 2) void k_proj_mma(const float* __restrict__ X) {
    extern __shared__ __align__(128) char smem[];
    const uint32_t smb = smem_u32(smem);

    const int bh = blockIdx.y, b = bh / NH, h = bh % NH;
    const int n0 = blockIdx.x * 128;
    const int tid = threadIdx.x, wid = tid >> 5, lid = tid & 31;
    const int mw = wid & 3, nw = wid >> 2;
    const int g = lid >> 2, t4 = lid & 3;
    const int mrow = mw * 32, ncol = nw * 32;
    const int l7 = lid & 7;
    const int r8  = (lid & 8)  ? 8 : 0;
    const int r16 = (lid & 16) ? 8 : 0;

    const float* Xb = X + ((size_t)b * NSEQ + n0) * HIDD;
    const uint32_t* Wh = g_Wh + (size_t)h * HD * (HIDD / 2);
    const uint32_t* Wl = g_Wl + (size_t)h * HD * (HIDD / 2);

    auto issue = [&](int ki) {
        const uint32_t xf = smb + PJ_XF + (ki & 1) * PJ_XFST;
        const uint32_t wb = smb + PJ_W + (ki & 1) * PJ_WST;
        const int k0 = ki * 32;       // float offset of k-tile
        const int k4 = ki * 16;       // u32-pair offset for W
        // fp32 X tile: 128 rows x 128B
#pragma unroll
        for (int it = 0; it < 4; it++) {
            int f = tid + it * 256;
            int r = f >> 3, c = f & 7;
            asm volatile("cp.async.cg.shared.global [%0], [%1], 16;"
                         :: "r"(xf + (uint32_t)(r * 144 + c * 16)),
                            "l"(Xb + (size_t)r * HIDD + k0 + c * 4));
        }
        // Wh/Wl: 64 rows x 64B each
        {
            int r = tid >> 2, c = tid & 3;
            uint32_t d = (uint32_t)(r * 80 + c * 16);
            asm volatile("cp.async.cg.shared.global [%0], [%1], 16;"
                         :: "r"(wb + d), "l"(Wh + (size_t)r * 384 + k4 + c * 4));
            asm volatile("cp.async.cg.shared.global [%0], [%1], 16;"
                         :: "r"(wb + 5120 + d), "l"(Wl + (size_t)r * 384 + k4 + c * 4));
        }
        asm volatile("cp.async.commit_group;" ::: "memory");
    };

    float acc[2][4][4];
#pragma unroll
    for (int mi = 0; mi < 2; mi++)
#pragma unroll
        for (int nj = 0; nj < 4; nj++)
#pragma unroll
            for (int r = 0; r < 4; r++) acc[mi][nj][r] = 0.f;

    const uint32_t aro = (uint32_t)((mrow + l7 + r8) * 80 + r16 * 2);
    const uint32_t bro = (uint32_t)((ncol + l7 + r16) * 80 + r8 * 2);

    // conversion lane mapping: thread -> (row, k-half)
    const int cvr = tid >> 1, cvh = tid & 1;

    issue(0);
#pragma unroll 1
    for (int ki = 0; ki < NKIT; ki++) {
        asm volatile("cp.async.wait_group 0;" ::: "memory");
        __syncthreads();              // data ready + prior mma reads done
        if (ki + 1 < NKIT) issue(ki + 1);

        // ---- in-kernel split: fp32 -> bf16 h/l (16 floats/thread) ----
        {
            const char* xf = smem + PJ_XF + (ki & 1) * PJ_XFST
                           + cvr * 144 + cvh * 64;
            float4 v0 = *(const float4*)(xf);
            float4 v1 = *(const float4*)(xf + 16);
            float4 v2 = *(const float4*)(xf + 32);
            float4 v3 = *(const float4*)(xf + 48);
            uint4 hq0, lq0, hq1, lq1;
            split2(v0.x, v0.y, hq0.x, lq0.x);
            split2(v0.z, v0.w, hq0.y, lq0.y);
            split2(v1.x, v1.y, hq0.z, lq0.z);
            split2(v1.z, v1.w, hq0.w, lq0.w);
            split2(v2.x, v2.y, hq1.x, lq1.x);
            split2(v2.z, v2.w, hq1.y, lq1.y);
            split2(v3.x, v3.y, hq1.z, lq1.z);
            split2(v3.z, v3.w, hq1.w, lq1.w);
            char* xh = smem + PJ_XH + cvr * 80 + cvh * 32;
            char* xl = smem + PJ_XL + cvr * 80 + cvh * 32;
            *(uint4*)(xh)      = hq0;
            *(uint4*)(xh + 16) = hq1;
            *(uint4*)(xl)      = lq0;
            *(uint4*)(xl + 16) = lq1;
        }
        __syncthreads();              // converted tiles visible to ldmatrix

        const uint32_t wb = smb + PJ_W + (ki & 1) * PJ_WST;
#pragma unroll
        for (int c16 = 0; c16 < 2; c16++) {
            const uint32_t off = c16 * 32;
            uint32_t xh0[4], xh1[4], xl0[4], xl1[4];
            ldsm4(xh0, smb + PJ_XH + aro + off);
            ldsm4(xh1, smb + PJ_XH + aro + 16 * 80 + off);
            ldsm4(xl0, smb + PJ_XL + aro + off);
            ldsm4(xl1, smb + PJ_XL + aro + 16 * 80 + off);
            uint32_t wh0[4], wh1[4], wl0[4], wl1[4];
            ldsm4(wh0, wb + bro + off);
            ldsm4(wh1, wb + bro + 16 * 80 + off);
            ldsm4(wl0, wb + 5120 + bro + off);
            ldsm4(wl1, wb + 5120 + bro + 16 * 80 + off);
            mma16(acc[0][0], xh0, wh0);     mma16(acc[0][0], xh0, wl0);
            mma16(acc[0][0], xl0, wh0);
            mma16(acc[0][1], xh0, wh0 + 2); mma16(acc[0][1], xh0, wl0 + 2);
            mma16(acc[0][1], xl0, wh0 + 2);
            mma16(acc[0][2], xh0, wh1);     mma16(acc[0][2], xh0, wl1);
            mma16(acc[0][2], xl0, wh1);
            mma16(acc[0][3], xh0, wh1 + 2); mma16(acc[0][3], xh0, wl1 + 2);
            mma16(acc[0][3], xl0, wh1 + 2);
            mma16(acc[1][0], xh1, wh0);     mma16(acc[1][0], xh1, wl0);
            mma16(acc[1][0], xl1, wh0);
            mma16(acc[1][1], xh1, wh0 + 2); mma16(acc[1][1], xh1, wl0 + 2);
            mma16(acc[1][1], xl1, wh0 + 2);
            mma16(acc[1][2], xh1, wh1);     mma16(acc[1][2], xh1, wl1);
            mma16(acc[1][2], xl1, wh1);
            mma16(acc[1][3], xh1, wh1 + 2); mma16(acc[1][3], xh1, wl1 + 2);
            mma16(acc[1][3], xl1, wh1 + 2);
        }
    }

    // epilogue: fp16 t
    uint32_t* T16 = g_t16 + ((size_t)bh * NSEQ + n0) * (HD / 2);
#pragma unroll
    for (int mi = 0; mi < 2; mi++) {
        int r0 = mrow + mi * 16 + g;
#pragma unroll
        for (int nj = 0; nj < 4; nj++) {
            int cu = (ncol + nj * 8) / 2 + t4;
            T16[(size_t)r0 * (HD / 2) + cu] =
                packf16(acc[mi][nj][0], acc[mi][nj][1]);
            T16[(size_t)(r0 + 8) * (HD / 2) + cu] =
                packf16(acc[mi][nj][2], acc[mi][nj][3]);
        }
    }
}

// ---------------------------------------------------------------------------
// Kernel 2: all-fp16 flash attention; exp via ex2.approx.f16x2 (unchanged R15).
// ---------------------------------------------------------------------------
#define A_Q    0                    // 128 * 144 fp16
#define A_KV   18432                // 2 stages * 64*144
#define A_KVST 9216
#define A_OB   36864                // float[2][64]
#define A_OL   37376                // float[128]
#define A_SM   37888

#define CE 0.052058774f             // 768^-0.5 * log2(e)

__global__ __launch_bounds__(256, 2) void k_attn7(const int* __restrict__ amask,
                                                  float* __restrict__ out) {
    extern __shared__ __align__(128) char smem[];
    const uint32_t smb = smem_u32(smem);

    const int bh = blockIdx.y, b = bh / NH, h = bh % NH;
    const int q0 = blockIdx.x * QT;
    const int tid = threadIdx.x, wid = tid >> 5, lid = tid & 31;
    const int g = lid >> 2, t4 = lid & 3;
    const int w16 = wid * 16;
    const int l7 = lid & 7;
    const int r8  = (lid & 8)  ? 8 : 0;
    const int r16 = (lid & 16) ? 8 : 0;

    const uint32_t* T16 = g_t16 + (size_t)bh * NSEQ * (HD / 2);
    const int* mb = amask + (size_t)b * NSEQ;
    float* biasf = (float*)(smem + A_OB);

#pragma unroll
    for (int it = 0; it < 4; it++) {
        int f = tid + it * 256;
        int r = f >> 3, c = f & 7;
        uint32_t dst = smb + A_Q + (uint32_t)(r * 144 + c * 16);
        asm volatile("cp.async.cg.shared.global [%0], [%1], 16;"
                     :: "r"(dst), "l"(T16 + (size_t)(q0 + r) * 32 + c * 4));
    }
#pragma unroll
    for (int it = 0; it < 2; it++) {
        int f = tid + it * 256;
        int r = f >> 3, c = f & 7;
        uint32_t dst = smb + A_KV + (uint32_t)(r * 144 + c * 16);
        asm volatile("cp.async.cg.shared.global [%0], [%1], 16;"
                     :: "r"(dst), "l"(T16 + (size_t)r * 32 + c * 4));
    }
    asm volatile("cp.async.commit_group;" ::: "memory");
    if (tid < 64) biasf[tid] = (mb[tid] == 0) ? -3000.f : 0.f;

    float rs0 = 0.f, rs1 = 0.f;
    float oacc[4][2][4];
#pragma unroll
    for (int me = 0; me < 4; me++)
#pragma unroll
        for (int n = 0; n < 2; n++)
#pragma unroll
            for (int r = 0; r < 4; r++) oacc[me][n][r] = 0.f;

    const uint32_t qro = (uint32_t)((w16 + l7 + r8) * 144 + r16 * 2);
    const uint32_t kro = (uint32_t)((l7 + r16) * 144 + r8 * 2);

#pragma unroll 1
    for (int i = 0; i < NIT; i++) {
        asm volatile("cp.async.wait_group 0;" ::: "memory");
        __syncthreads();

        if (i + 1 < NIT) {
            int j0 = (i + 1) * KT;
            uint32_t kst = A_KV + ((i + 1) & 1) * A_KVST;
#pragma unroll
            for (int it = 0; it < 2; it++) {
                int f = tid + it * 256;
                int r = f >> 3, c = f & 7;
                uint32_t dst = smb + kst + (uint32_t)(r * 144 + c * 16);
                asm volatile("cp.async.cg.shared.global [%0], [%1], 16;"
                             :: "r"(dst), "l"(T16 + (size_t)(j0 + r) * 32 + c * 4));
            }
            asm volatile("cp.async.commit_group;" ::: "memory");
            if (tid < 64)
                biasf[((i + 1) & 1) * 64 + tid] =
                    (mb[j0 + tid] == 0) ? -3000.f : 0.f;
        }

        const uint32_t kvb = smb + A_KV + (i & 1) * A_KVST;

        float sacc[8][4];
#pragma unroll
        for (int kg = 0; kg < 8; kg++)
#pragma unroll
            for (int r = 0; r < 4; r++) sacc[kg][r] = 0.f;

#pragma unroll
        for (int kb = 0; kb < 4; kb++) {
            uint32_t qf[4];
            ldsm4(qf, smb + A_Q + qro + kb * 32);
#pragma unroll
            for (int kt = 0; kt < 4; kt++) {
                uint32_t kf[4];
                ldsm4(kf, kvb + (uint32_t)(kt * 16 * 144) + kro + kb * 32);
                mma16h(sacc[kt * 2],     qf, kf);
                mma16h(sacc[kt * 2 + 1], qf, kf + 2);
            }
        }

        uint32_t u01[8], u23[8];
        uint32_t hs0 = 0u, hs1 = 0u;
        const float* bi = biasf + (i & 1) * 64;
#pragma unroll
        for (int kg = 0; kg < 8; kg++) {
            float bx = bi[kg * 8 + 2 * t4];
            float by = bi[kg * 8 + 2 * t4 + 1];
            float* c = sacc[kg];
            uint32_t e01 = packf16(fmaf(c[0], CE, bx), fmaf(c[1], CE, by));
            uint32_t e23 = packf16(fmaf(c[2], CE, bx), fmaf(c[3], CE, by));
            u01[kg] = ex2h2(e01);
            u23[kg] = ex2h2(e23);
            hs0 = hadd2u(hs0, u01[kg]);
            hs1 = hadd2u(hs1, u23[kg]);
        }
        {
            __half2 h0 = *reinterpret_cast<__half2*>(&hs0);
            __half2 h1 = *reinterpret_cast<__half2*>(&hs1);
            rs0 += __low2float(h0) + __high2float(h0);
            rs1 += __low2float(h1) + __high2float(h1);
        }

#pragma unroll
        for (int kt = 0; kt < 4; kt++) {
            uint32_t b0[2] = { u01[kt * 2], u01[kt * 2 + 1] };
            uint32_t b1[2] = { u23[kt * 2], u23[kt * 2 + 1] };
#pragma unroll
            for (int me = 0; me < 4; me++) {
                uint32_t ah[4];
                ldsm4t(ah, kvb + (uint32_t)((kt * 16 + l7 + r16) * 144
                                            + (me * 16 + r8) * 2));
                mma16h(oacc[me][0], ah, b0);
                mma16h(oacc[me][1], ah, b1);
            }
        }
    }

    rs0 += __shfl_xor_sync(0xffffffffu, rs0, 1);
    rs0 += __shfl_xor_sync(0xffffffffu, rs0, 2);
    rs1 += __shfl_xor_sync(0xffffffffu, rs1, 1);
    rs1 += __shfl_xor_sync(0xffffffffu, rs1, 2);
    float* lred = (float*)(smem + A_OL);
    if (t4 == 0) {
        lred[w16 + g] = rs0;
        lred[w16 + 8 + g] = rs1;
    }
    __syncthreads();

    const int qa = w16 + 2 * t4;
    const float inv0 = 1.f / lred[qa];
    const float inv1 = 1.f / lred[qa + 1];
    const float inv2 = 1.f / lred[qa + 8];
    const float inv3 = 1.f / lred[qa + 9];
    float* ob = out + ((size_t)b * NSEQ + q0 + qa) * (NH * HD) + h * HD;
#pragma unroll
    for (int me = 0; me < 4; me++) {
        int e0 = me * 16 + g;
        ob[e0]                   = oacc[me][0][0] * inv0;
        ob[NH * HD + e0]         = oacc[me][0][1] * inv1;
        ob[e0 + 8]               = oacc[me][0][2] * inv0;
        ob[NH * HD + e0 + 8]     = oacc[me][0][3] * inv1;
        ob[8 * NH * HD + e0]     = oacc[me][1][0] * inv2;
        ob[9 * NH * HD + e0]     = oacc[me][1][1] * inv3;
        ob[8 * NH * HD + e0 + 8] = oacc[me][1][2] * inv2;
        ob[9 * NH * HD + e0 + 8] = oacc[me][1][3] * inv3;
    }
}

// ---------------------------------------------------------------------------
extern "C" void kernel_launch(void* const* d_in, const int* in_sizes, int n_in,
                              void* d_out, int out_size) {
    const float* hidden = (const float*)d_in[0];
    const int*   amask  = (const int*)d_in[1];
    const float* Wt     = (const float*)d_in[2];
    const float* Wa     = (const float*)d_in[3];
    float* out = (float*)d_out;

    k_pre<<<WC_BLKS, 256>>>(Wt, Wa);

    cudaFuncSetAttribute(k_proj_mma, cudaFuncAttributeMaxDynamicSharedMemorySize,
                         PROJ_SMEM_BYTES);
    k_proj_mma<<<dim3(NSEQ / 128, NB * NH), 256, PROJ_SMEM_BYTES>>>(hidden);

    cudaFuncSetAttribute(k_attn7, cudaFuncAttributeMaxDynamicSharedMemorySize,
                         A_SM);
    k_attn7<<<dim3(NSEQ / QT, NB * NH), 256, A_SM>>>(amask, out);
}

// round 17
// speedup vs baseline: 1.5076x; 1.0124x over previous
#include <cuda_runtime.h>
#include <cuda_bf16.h>
#include <cuda_fp16.h>
#include <cstdint>

#define NB    8
#define NSEQ  1024
#define HIDD  768
#define NH    12
#define LR    256
#define HD    64

#define QT    128
#define KT    64
#define NIT   (NSEQ / KT)

// scratch (no cudaMalloc allowed)
__device__ uint32_t g_Wh[NH * HD * (HIDD / 2)];      // Wc bf16 hi, k-pair packed
__device__ uint32_t g_Wl[NH * HD * (HIDD / 2)];      // Wc bf16 lo
__device__ uint32_t g_t16[NB * NH * NSEQ * (HD / 2)];// t fp16 e-pairs (q=k=v)

// ---------------------------------------------------------------------------
// helpers
// ---------------------------------------------------------------------------
__device__ __forceinline__ uint32_t smem_u32(const void* p) {
    uint32_t a;
    asm("{ .reg .u64 t; cvta.to.shared.u64 t, %1; cvt.u32.u64 %0, t; }"
        : "=r"(a) : "l"(p));
    return a;
}
__device__ __forceinline__ uint32_t packbf(float lo, float hi) {
    uint32_t r;
    asm("cvt.rn.bf16x2.f32 %0, %1, %2;" : "=r"(r) : "f"(hi), "f"(lo));
    return r;
}
__device__ __forceinline__ uint32_t packf16(float lo, float hi) {
    uint32_t r;
    asm("cvt.rn.f16x2.f32 %0, %1, %2;" : "=r"(r) : "f"(hi), "f"(lo));
    return r;
}
__device__ __forceinline__ void split2(float x0, float x1,
                                       uint32_t& hp, uint32_t& lp) {
    hp = packbf(x0, x1);
    float h0 = __uint_as_float(hp << 16);
    float h1 = __uint_as_float(hp & 0xffff0000u);
    lp = packbf(x0 - h0, x1 - h1);
}
__device__ __forceinline__ uint32_t ex2h2(uint32_t x) {
    uint32_t r; asm("ex2.approx.f16x2 %0, %1;" : "=r"(r) : "r"(x)); return r;
}
__device__ __forceinline__ uint32_t hadd2u(uint32_t a, uint32_t b) {
    uint32_t r; asm("add.rn.f16x2 %0, %1, %2;" : "=r"(r) : "r"(a), "r"(b));
    return r;
}
// bf16 m16n8k16 (projection)
__device__ __forceinline__ void mma16(float* c, const uint32_t* a, const uint32_t* b) {
    asm volatile(
        "mma.sync.aligned.m16n8k16.row.col.f32.bf16.bf16.f32 "
        "{%0,%1,%2,%3}, {%4,%5,%6,%7}, {%8,%9}, {%0,%1,%2,%3};"
        : "+f"(c[0]), "+f"(c[1]), "+f"(c[2]), "+f"(c[3])
        : "r"(a[0]), "r"(a[1]), "r"(a[2]), "r"(a[3]), "r"(b[0]), "r"(b[1]));
}
// fp16 m16n8k16 (attention S and PV)
__device__ __forceinline__ void mma16h(float* c, const uint32_t* a, const uint32_t* b) {
    asm volatile(
        "mma.sync.aligned.m16n8k16.row.col.f32.f16.f16.f32 "
        "{%0,%1,%2,%3}, {%4,%5,%6,%7}, {%8,%9}, {%0,%1,%2,%3};"
        : "+f"(c[0]), "+f"(c[1]), "+f"(c[2]), "+f"(c[3])
        : "r"(a[0]), "r"(a[1]), "r"(a[2]), "r"(a[3]), "r"(b[0]), "r"(b[1]));
}
__device__ __forceinline__ void ldsm4(uint32_t* r, uint32_t a) {
    asm volatile("ldmatrix.sync.aligned.m8n8.x4.b16 {%0,%1,%2,%3}, [%4];"
        : "=r"(r[0]), "=r"(r[1]), "=r"(r[2]), "=r"(r[3]) : "r"(a));
}
__device__ __forceinline__ void ldsm4t(uint32_t* r, uint32_t a) {
    asm volatile("ldmatrix.sync.aligned.m8n8.x4.trans.b16 {%0,%1,%2,%3}, [%4];"
        : "=r"(r[0]), "=r"(r[1]), "=r"(r[2]), "=r"(r[3]) : "r"(a));
}

// ---------------------------------------------------------------------------
// Kernel 0: Wc = Wa@Wt (fp32 exact) -> bf16 h/l.
// Single wave: 144 blocks x 512 threads, d-chunk 64, 2-stage cp.async.
// ---------------------------------------------------------------------------
#define WC_BLKS (NH * 12)     // 144

__global__ __launch_bounds__(512) void k_pre(const float* __restrict__ Wt,
                                             const float* __restrict__ Wa) {
    const int tid = threadIdx.x;
    const int h  = blockIdx.x / 12;
    const int d0 = (blockIdx.x % 12) * 64;

    __shared__ float Wa_s[2][64 * 36];
    __shared__ float Wt_s[2][32 * 68];
    const uint32_t wa_b = smem_u32(Wa_s);
    const uint32_t wt_b = smem_u32(Wt_s);

    const int te = tid / 16;   // 0..31, 2 e-rows each
    const int td = tid % 16;   // 4 d-cols each

    auto issue = [&](int it) {
        const int st = it & 1;
        const int l0 = it * 32;
        {   // Wa tile 64x32: 512 float4, 1/thread
            int e = tid / 8, l4 = tid % 8;
            asm volatile("cp.async.cg.shared.global [%0], [%1], 16;"
                :: "r"(wa_b + (uint32_t)(st * 64 * 36 + e * 36 + l4 * 4) * 4u),
                   "l"(Wa + ((size_t)h * 64 + e) * LR + l0 + l4 * 4));
        }
        {   // Wt tile 32x64: 512 float4, 1/thread
            int l = tid / 16, c4 = tid % 16;
            asm volatile("cp.async.cg.shared.global [%0], [%1], 16;"
                :: "r"(wt_b + (uint32_t)(st * 32 * 68 + l * 68 + c4 * 4) * 4u),
                   "l"(Wt + ((size_t)h * LR + l0 + l) * HIDD + d0 + c4 * 4));
        }
        asm volatile("cp.async.commit_group;" ::: "memory");
    };

    float acc[2][4];
#pragma unroll
    for (int i = 0; i < 2; i++)
#pragma unroll
        for (int j = 0; j < 4; j++) acc[i][j] = 0.f;

    issue(0);
#pragma unroll 1
    for (int it = 0; it < LR / 32; it++) {
        asm volatile("cp.async.wait_group 0;" ::: "memory");
        __syncthreads();
        if (it + 1 < LR / 32) issue(it + 1);

        const float* Was = Wa_s[it & 1];
        const float* Wts = Wt_s[it & 1];
#pragma unroll
        for (int l = 0; l < 32; l++) {
            float a0 = Was[(te * 2) * 36 + l];
            float a1 = Was[(te * 2 + 1) * 36 + l];
            float w[4];
            *(float4*)w = *(const float4*)&Wts[l * 68 + td * 4];
#pragma unroll
            for (int j = 0; j < 4; j++) {
                acc[0][j] = fmaf(a0, w[j], acc[0][j]);
                acc[1][j] = fmaf(a1, w[j], acc[1][j]);
            }
        }
        __syncthreads();
    }
#pragma unroll
    for (int i = 0; i < 2; i++) {
        const int e = te * 2 + i;
        uint32_t h0, l0u, h1, l1u;
        split2(acc[i][0], acc[i][1], h0, l0u);
        split2(acc[i][2], acc[i][3], h1, l1u);
        size_t base = ((size_t)h * HD + e) * (HIDD / 2) + d0 / 2 + td * 2;
        *(uint2*)&g_Wh[base] = make_uint2(h0, h1);
        *(uint2*)&g_Wl[base] = make_uint2(l0u, l1u);
    }
}

// ---------------------------------------------------------------------------
// Kernel 1: t = X * Wc^T, 3-term bf16 split with in-kernel X split (R16).
// ---------------------------------------------------------------------------
#define PJ_XF   0                      // 2 stages * 128*144 (fp32 X tile)
#define PJ_XFST 18432
#define PJ_XH   36864                  // 128*80  (converted bf16 hi, single)
#define PJ_XL   47104                  // 128*80  (converted bf16 lo, single)
#define PJ_W    57344                  // 2 stages * (Wh 64*80 | Wl +5120)
#define PJ_WST  10240
#define PROJ_SMEM_BYTES 77824
#define NKIT  (HIDD / 32)              // 24

__global__ __launch_bounds__(256, 2) void k_proj_mma(const float* __restrict__ X) {
    extern __shared__ __align__(128) char smem[];
    const uint32_t smb = smem_u32(smem);

    const int bh = blockIdx.y, b = bh / NH, h = bh % NH;
    const int n0 = blockIdx.x * 128;
    const int tid = threadIdx.x, wid = tid >> 5, lid = tid & 31;
    const int mw = wid & 3, nw = wid >> 2;
    const int g = lid >> 2, t4 = lid & 3;
    const int mrow = mw * 32, ncol = nw * 32;
    const int l7 = lid & 7;
    const int r8  = (lid & 8)  ? 8 : 0;
    const int r16 = (lid & 16) ? 8 : 0;

    const float* Xb = X + ((size_t)b * NSEQ + n0) * HIDD;
    const uint32_t* Wh = g_Wh + (size_t)h * HD * (HIDD / 2);
    const uint32_t* Wl = g_Wl + (size_t)h * HD * (HIDD / 2);

    auto issue = [&](int ki) {
        const uint32_t xf = smb + PJ_XF + (ki & 1) * PJ_XFST;
        const uint32_t wb = smb + PJ_W + (ki & 1) * PJ_WST;
        const int k0 = ki * 32;
        const int k4 = ki * 16;
#pragma unroll
        for (int it = 0; it < 4; it++) {
            int f = tid + it * 256;
            int r = f >> 3, c = f & 7;
            asm volatile("cp.async.cg.shared.global [%0], [%1], 16;"
                         :: "r"(xf + (uint32_t)(r * 144 + c * 16)),
                            "l"(Xb + (size_t)r * HIDD + k0 + c * 4));
        }
        {
            int r = tid >> 2, c = tid & 3;
            uint32_t d = (uint32_t)(r * 80 + c * 16);
            asm volatile("cp.async.cg.shared.global [%0], [%1], 16;"
                         :: "r"(wb + d), "l"(Wh + (size_t)r * 384 + k4 + c * 4));
            asm volatile("cp.async.cg.shared.global [%0], [%1], 16;"
                         :: "r"(wb + 5120 + d), "l"(Wl + (size_t)r * 384 + k4 + c * 4));
        }
        asm volatile("cp.async.commit_group;" ::: "memory");
    };

    float acc[2][4][4];
#pragma unroll
    for (int mi = 0; mi < 2; mi++)
#pragma unroll
        for (int nj = 0; nj < 4; nj++)
#pragma unroll
            for (int r = 0; r < 4; r++) acc[mi][nj][r] = 0.f;

    const uint32_t aro = (uint32_t)((mrow + l7 + r8) * 80 + r16 * 2);
    const uint32_t bro = (uint32_t)((ncol + l7 + r16) * 80 + r8 * 2);

    const int cvr = tid >> 1, cvh = tid & 1;

    issue(0);
#pragma unroll 1
    for (int ki = 0; ki < NKIT; ki++) {
        asm volatile("cp.async.wait_group 0;" ::: "memory");
        __syncthreads();
        if (ki + 1 < NKIT) issue(ki + 1);

        {
            const char* xf = smem + PJ_XF + (ki & 1) * PJ_XFST
                           + cvr * 144 + cvh * 64;
            float4 v0 = *(const float4*)(xf);
            float4 v1 = *(const float4*)(xf + 16);
            float4 v2 = *(const float4*)(xf + 32);
            float4 v3 = *(const float4*)(xf + 48);
            uint4 hq0, lq0, hq1, lq1;
            split2(v0.x, v0.y, hq0.x, lq0.x);
            split2(v0.z, v0.w, hq0.y, lq0.y);
            split2(v1.x, v1.y, hq0.z, lq0.z);
            split2(v1.z, v1.w, hq0.w, lq0.w);
            split2(v2.x, v2.y, hq1.x, lq1.x);
            split2(v2.z, v2.w, hq1.y, lq1.y);
            split2(v3.x, v3.y, hq1.z, lq1.z);
            split2(v3.z, v3.w, hq1.w, lq1.w);
            char* xh = smem + PJ_XH + cvr * 80 + cvh * 32;
            char* xl = smem + PJ_XL + cvr * 80 + cvh * 32;
            *(uint4*)(xh)      = hq0;
            *(uint4*)(xh + 16) = hq1;
            *(uint4*)(xl)      = lq0;
            *(uint4*)(xl + 16) = lq1;
        }
        __syncthreads();

        const uint32_t wb = smb + PJ_W + (ki & 1) * PJ_WST;
#pragma unroll
        for (int c16 = 0; c16 < 2; c16++) {
            const uint32_t off = c16 * 32;
            uint32_t xh0[4], xh1[4], xl0[4], xl1[4];
            ldsm4(xh0, smb + PJ_XH + aro + off);
            ldsm4(xh1, smb + PJ_XH + aro + 16 * 80 + off);
            ldsm4(xl0, smb + PJ_XL + aro + off);
            ldsm4(xl1, smb + PJ_XL + aro + 16 * 80 + off);
            uint32_t wh0[4], wh1[4], wl0[4], wl1[4];
            ldsm4(wh0, wb + bro + off);
            ldsm4(wh1, wb + bro + 16 * 80 + off);
            ldsm4(wl0, wb + 5120 + bro + off);
            ldsm4(wl1, wb + 5120 + bro + 16 * 80 + off);
            mma16(acc[0][0], xh0, wh0);     mma16(acc[0][0], xh0, wl0);
            mma16(acc[0][0], xl0, wh0);
            mma16(acc[0][1], xh0, wh0 + 2); mma16(acc[0][1], xh0, wl0 + 2);
            mma16(acc[0][1], xl0, wh0 + 2);
            mma16(acc[0][2], xh0, wh1);     mma16(acc[0][2], xh0, wl1);
            mma16(acc[0][2], xl0, wh1);
            mma16(acc[0][3], xh0, wh1 + 2); mma16(acc[0][3], xh0, wl1 + 2);
            mma16(acc[0][3], xl0, wh1 + 2);
            mma16(acc[1][0], xh1, wh0);     mma16(acc[1][0], xh1, wl0);
            mma16(acc[1][0], xl1, wh0);
            mma16(acc[1][1], xh1, wh0 + 2); mma16(acc[1][1], xh1, wl0 + 2);
            mma16(acc[1][1], xl1, wh0 + 2);
            mma16(acc[1][2], xh1, wh1);     mma16(acc[1][2], xh1, wl1);
            mma16(acc[1][2], xl1, wh1);
            mma16(acc[1][3], xh1, wh1 + 2); mma16(acc[1][3], xh1, wl1 + 2);
            mma16(acc[1][3], xl1, wh1 + 2);
        }
    }

    uint32_t* T16 = g_t16 + ((size_t)bh * NSEQ + n0) * (HD / 2);
#pragma unroll
    for (int mi = 0; mi < 2; mi++) {
        int r0 = mrow + mi * 16 + g;
#pragma unroll
        for (int nj = 0; nj < 4; nj++) {
            int cu = (ncol + nj * 8) / 2 + t4;
            T16[(size_t)r0 * (HD / 2) + cu] =
                packf16(acc[mi][nj][0], acc[mi][nj][1]);
            T16[(size_t)(r0 + 8) * (HD / 2) + cu] =
                packf16(acc[mi][nj][2], acc[mi][nj][3]);
        }
    }
}

// ---------------------------------------------------------------------------
// Kernel 2: all-fp16 flash attention; exp via ex2.approx.f16x2 (unchanged).
// ---------------------------------------------------------------------------
#define A_Q    0                    // 128 * 144 fp16
#define A_KV   18432                // 2 stages * 64*144
#define A_KVST 9216
#define A_OB   36864                // float[2][64]
#define A_OL   37376                // float[128]
#define A_SM   37888

#define CE 0.052058774f             // 768^-0.5 * log2(e)

__global__ __launch_bounds__(256, 2) void k_attn7(const int* __restrict__ amask,
                                                  float* __restrict__ out) {
    extern __shared__ __align__(128) char smem[];
    const uint32_t smb = smem_u32(smem);

    const int bh = blockIdx.y, b = bh / NH, h = bh % NH;
    const int q0 = blockIdx.x * QT;
    const int tid = threadIdx.x, wid = tid >> 5, lid = tid & 31;
    const int g = lid >> 2, t4 = lid & 3;
    const int w16 = wid * 16;
    const int l7 = lid & 7;
    const int r8  = (lid & 8)  ? 8 : 0;
    const int r16 = (lid & 16) ? 8 : 0;

    const uint32_t* T16 = g_t16 + (size_t)bh * NSEQ * (HD / 2);
    const int* mb = amask + (size_t)b * NSEQ;
    float* biasf = (float*)(smem + A_OB);

#pragma unroll
    for (int it = 0; it < 4; it++) {
        int f = tid + it * 256;
        int r = f >> 3, c = f & 7;
        uint32_t dst = smb + A_Q + (uint32_t)(r * 144 + c * 16);
        asm volatile("cp.async.cg.shared.global [%0], [%1], 16;"
                     :: "r"(dst), "l"(T16 + (size_t)(q0 + r) * 32 + c * 4));
    }
#pragma unroll
    for (int it = 0; it < 2; it++) {
        int f = tid + it * 256;
        int r = f >> 3, c = f & 7;
        uint32_t dst = smb + A_KV + (uint32_t)(r * 144 + c * 16);
        asm volatile("cp.async.cg.shared.global [%0], [%1], 16;"
                     :: "r"(dst), "l"(T16 + (size_t)r * 32 + c * 4));
    }
    asm volatile("cp.async.commit_group;" ::: "memory");
    if (tid < 64) biasf[tid] = (mb[tid] == 0) ? -3000.f : 0.f;

    float rs0 = 0.f, rs1 = 0.f;
    float oacc[4][2][4];
#pragma unroll
    for (int me = 0; me < 4; me++)
#pragma unroll
        for (int n = 0; n < 2; n++)
#pragma unroll
            for (int r = 0; r < 4; r++) oacc[me][n][r] = 0.f;

    const uint32_t qro = (uint32_t)((w16 + l7 + r8) * 144 + r16 * 2);
    const uint32_t kro = (uint32_t)((l7 + r16) * 144 + r8 * 2);

#pragma unroll 1
    for (int i = 0; i < NIT; i++) {
        asm volatile("cp.async.wait_group 0;" ::: "memory");
        __syncthreads();

        if (i + 1 < NIT) {
            int j0 = (i + 1) * KT;
            uint32_t kst = A_KV + ((i + 1) & 1) * A_KVST;
#pragma unroll
            for (int it = 0; it < 2; it++) {
                int f = tid + it * 256;
                int r = f >> 3, c = f & 7;
                uint32_t dst = smb + kst + (uint32_t)(r * 144 + c * 16);
                asm volatile("cp.async.cg.shared.global [%0], [%1], 16;"
                             :: "r"(dst), "l"(T16 + (size_t)(j0 + r) * 32 + c * 4));
            }
            asm volatile("cp.async.commit_group;" ::: "memory");
            if (tid < 64)
                biasf[((i + 1) & 1) * 64 + tid] =
                    (mb[j0 + tid] == 0) ? -3000.f : 0.f;
        }

        const uint32_t kvb = smb + A_KV + (i & 1) * A_KVST;

        float sacc[8][4];
#pragma unroll
        for (int kg = 0; kg < 8; kg++)
#pragma unroll
            for (int r = 0; r < 4; r++) sacc[kg][r] = 0.f;

#pragma unroll
        for (int kb = 0; kb < 4; kb++) {
            uint32_t qf[4];
            ldsm4(qf, smb + A_Q + qro + kb * 32);
#pragma unroll
            for (int kt = 0; kt < 4; kt++) {
                uint32_t kf[4];
                ldsm4(kf, kvb + (uint32_t)(kt * 16 * 144) + kro + kb * 32);
                mma16h(sacc[kt * 2],     qf, kf);
                mma16h(sacc[kt * 2 + 1], qf, kf + 2);
            }
        }

        uint32_t u01[8], u23[8];
        uint32_t hs0 = 0u, hs1 = 0u;
        const float* bi = biasf + (i & 1) * 64;
#pragma unroll
        for (int kg = 0; kg < 8; kg++) {
            float bx = bi[kg * 8 + 2 * t4];
            float by = bi[kg * 8 + 2 * t4 + 1];
            float* c = sacc[kg];
            uint32_t e01 = packf16(fmaf(c[0], CE, bx), fmaf(c[1], CE, by));
            uint32_t e23 = packf16(fmaf(c[2], CE, bx), fmaf(c[3], CE, by));
            u01[kg] = ex2h2(e01);
            u23[kg] = ex2h2(e23);
            hs0 = hadd2u(hs0, u01[kg]);
            hs1 = hadd2u(hs1, u23[kg]);
        }
        {
            __half2 h0 = *reinterpret_cast<__half2*>(&hs0);
            __half2 h1 = *reinterpret_cast<__half2*>(&hs1);
            rs0 += __low2float(h0) + __high2float(h0);
            rs1 += __low2float(h1) + __high2float(h1);
        }

#pragma unroll
        for (int kt = 0; kt < 4; kt++) {
            uint32_t b0[2] = { u01[kt * 2], u01[kt * 2 + 1] };
            uint32_t b1[2] = { u23[kt * 2], u23[kt * 2 + 1] };
#pragma unroll
            for (int me = 0; me < 4; me++) {
                uint32_t ah[4];
                ldsm4t(ah, kvb + (uint32_t)((kt * 16 + l7 + r16) * 144
                                            + (me * 16 + r8) * 2));
                mma16h(oacc[me][0], ah, b0);
                mma16h(oacc[me][1], ah, b1);
            }
        }
    }

    rs0 += __shfl_xor_sync(0xffffffffu, rs0, 1);
    rs0 += __shfl_xor_sync(0xffffffffu, rs0, 2);
    rs1 += __shfl_xor_sync(0xffffffffu, rs1, 1);
    rs1 += __shfl_xor_sync(0xffffffffu, rs1, 2);
    float* lred = (float*)(smem + A_OL);
    if (t4 == 0) {
        lred[w16 + g] = rs0;
        lred[w16 + 8 + g] = rs1;
    }
    __syncthreads();

    const int qa = w16 + 2 * t4;
    const float inv0 = 1.f / lred[qa];
    const float inv1 = 1.f / lred[qa + 1];
    const float inv2 = 1.f / lred[qa + 8];
    const float inv3 = 1.f / lred[qa + 9];
    float* ob = out + ((size_t)b * NSEQ + q0 + qa) * (NH * HD) + h * HD;
#pragma unroll
    for (int me = 0; me < 4; me++) {
        int e0 = me * 16 + g;
        ob[e0]                   = oacc[me][0][0] * inv0;
        ob[NH * HD + e0]         = oacc[me][0][1] * inv1;
        ob[e0 + 8]               = oacc[me][0][2] * inv0;
        ob[NH * HD + e0 + 8]     = oacc[me][0][3] * inv1;
        ob[8 * NH * HD + e0]     = oacc[me][1][0] * inv2;
        ob[9 * NH * HD + e0]     = oacc[me][1][1] * inv3;
        ob[8 * NH * HD + e0 + 8] = oacc[me][1][2] * inv2;
        ob[9 * NH * HD + e0 + 8] = oacc[me][1][3] * inv3;
    }
}

// ---------------------------------------------------------------------------
extern "C" void kernel_launch(void* const* d_in, const int* in_sizes, int n_in,
                              void* d_out, int out_size) {
    const float* hidden = (const float*)d_in[0];
    const int*   amask  = (const int*)d_in[1];
    const float* Wt     = (const float*)d_in[2];
    const float* Wa     = (const float*)d_in[3];
    float* out = (float*)d_out;

    k_pre<<<WC_BLKS, 512>>>(Wt, Wa);

    cudaFuncSetAttribute(k_proj_mma, cudaFuncAttributeMaxDynamicSharedMemorySize,
                         PROJ_SMEM_BYTES);
    k_proj_mma<<<dim3(NSEQ / 128, NB * NH), 256, PROJ_SMEM_BYTES>>>(hidden);

    cudaFuncSetAttribute(k_attn7, cudaFuncAttributeMaxDynamicSharedMemorySize,
                         A_SM);
    k_attn7<<<dim3(NSEQ / QT, NB * NH), 256, A_SM>>>(amask, out);
}